// round 4
// baseline (speedup 1.0000x reference)
#include <cuda_runtime.h>
#include <math.h>

#define NMAX 100000
#define EMAX 1000000

// Scratch (module-static, no runtime allocation):
__device__ float4 g_q[NMAX * 3];       // per-node frame (3 cols), valid flag in [0].w
__device__ float4 g_nf[NMAX];          // per-node 4 features
__device__ float4 g_feat[EMAX * 6];    // per-edge 24 floats (23 feats + pad)

struct F3 { float x, y, z; };
__device__ __forceinline__ F3 mk3(float a, float b, float c) { F3 r; r.x = a; r.y = b; r.z = c; return r; }
__device__ __forceinline__ F3 sub3(F3 a, F3 b) { return mk3(a.x - b.x, a.y - b.y, a.z - b.z); }
__device__ __forceinline__ float dot3(F3 a, F3 b) { return a.x * b.x + a.y * b.y + a.z * b.z; }
__device__ __forceinline__ F3 cross3(F3 a, F3 b) {
    return mk3(a.y * b.z - a.z * b.y, a.z * b.x - a.x * b.z, a.x * b.y - a.y * b.x);
}
__device__ __forceinline__ F3 nrm3(F3 a) {
    float n = sqrtf(dot3(a, a));
    float s = 1.0f / fmaxf(n, 1e-12f);
    return mk3(a.x * s, a.y * s, a.z * s);
}
__device__ __forceinline__ float signf_(float x) { return (float)((x > 0.0f) - (x < 0.0f)); }

// packed f32x2 helpers
__device__ __forceinline__ unsigned long long dup2(float f) {
    unsigned long long p;
    unsigned u = __float_as_uint(f);
    asm("mov.b64 %0, {%1, %1};" : "=l"(p) : "r"(u));
    return p;
}
__device__ __forceinline__ unsigned long long pack2(float a, float b) {
    unsigned long long p;
    unsigned ua = __float_as_uint(a), ub = __float_as_uint(b);
    asm("mov.b64 %0, {%1, %2};" : "=l"(p) : "r"(ua), "r"(ub));
    return p;
}
__device__ __forceinline__ void unpack2(unsigned long long p, float& a, float& b) {
    unsigned ua, ub;
    asm("mov.b64 {%0, %1}, %2;" : "=r"(ua), "=r"(ub) : "l"(p));
    a = __uint_as_float(ua); b = __uint_as_float(ub);
}
__device__ __forceinline__ void ffma2(unsigned long long& d, unsigned long long a, unsigned long long b) {
    asm("fma.rn.f32x2 %0, %1, %2, %0;" : "+l"(d) : "l"(a), "l"(b));
}

// ---------------------------------------------------------------------------
// Kernel 1: per-node geometry -> node feats (4) + frame Q (3 cols) + valid
// ---------------------------------------------------------------------------
__global__ void k_node_geom(const float* __restrict__ X, const int* __restrict__ batch, int N)
{
    int i = blockIdx.x * blockDim.x + threadIdx.x;
    if (i >= N) return;

    auto ldx = [&](int j) -> F3 {
        j = j < 0 ? 0 : (j > N - 1 ? N - 1 : j);
        return mk3(X[3 * j], X[3 * j + 1], X[3 * j + 2]);
    };
    F3 xm1 = ldx(i - 1), x0 = ldx(i), xp1 = ldx(i + 1), xp2 = ldx(i + 2);

    int bi   = (i > 0)     && (batch[i] != batch[i - 1]);
    int bip1 = (i + 1 < N) && (batch[i + 1] != batch[i]);
    int bip2 = (i + 2 < N) && (batch[i + 2] != batch[i + 1]);
    bool bad_a = bi || bip1 || (i == 0) || (i == N - 1);
    bool bad_d = bi || bip1 || bip2 || (i == 0) || (i >= N - 2);

    F3 Um = nrm3(sub3(x0,  xm1));
    F3 Uc = nrm3(sub3(xp1, x0));
    F3 Up = nrm3(sub3(xp2, xp1));

    F3 c1 = nrm3(cross3(Um, Uc));
    F3 c2 = nrm3(cross3(Uc, Up));
    float cosd = fminf(fmaxf(dot3(c1, c2), -1.0f + 1e-6f), 1.0f - 1e-6f);
    float sg = signf_(dot3(c2, Um));
    float sdih = sg * sqrtf(fmaxf(1.0f - cosd * cosd, 0.0f));
    float cdih = (sg == 0.0f) ? 1.0f : cosd;

    F3 d0 = nrm3(sub3(xm1, x0));
    F3 d1 = nrm3(sub3(xp1, x0));
    float cosa = dot3(d0, d1);
    float sina = sqrtf(1.0f - cosa * cosa + 1e-6f);

    float4 nf;
    nf.x = bad_d ? 0.0f : sdih;
    nf.y = bad_d ? 0.0f : cdih;
    nf.z = bad_a ? 0.0f : sina;
    nf.w = bad_a ? 0.0f : cosa;
    g_nf[i] = nf;

    F3 bv = nrm3(sub3(Um, Uc));
    F3 nv = nrm3(cross3(Um, Uc));
    F3 cv = cross3(bv, nv);
    float m = bad_a ? 0.0f : 1.0f;
    g_q[i * 3 + 0] = make_float4(bv.x * m, bv.y * m, bv.z * m, m);
    g_q[i * 3 + 1] = make_float4(nv.x * m, nv.y * m, nv.z * m, 0.0f);
    g_q[i * 3 + 2] = make_float4(cv.x * m, cv.y * m, cv.z * m, 0.0f);
}

// ---------------------------------------------------------------------------
// Warp LayerNorm helper: lane owns 4 contiguous columns
// ---------------------------------------------------------------------------
__device__ __forceinline__ void ln_store(float4 a, float4 gg, float4 bt, float* __restrict__ dst)
{
    float s1 = a.x + a.y + a.z + a.w;
    float s2 = a.x * a.x + a.y * a.y + a.z * a.z + a.w * a.w;
#pragma unroll
    for (int o = 16; o > 0; o >>= 1) {
        s1 += __shfl_xor_sync(0xffffffffu, s1, o);
        s2 += __shfl_xor_sync(0xffffffffu, s2, o);
    }
    float mean = s1 * (1.0f / 128.0f);
    float var  = fmaxf(s2 * (1.0f / 128.0f) - mean * mean, 0.0f);
    float inv  = rsqrtf(var + 1e-5f);
    float4 o4;
    o4.x = (a.x - mean) * inv * gg.x + bt.x;
    o4.y = (a.y - mean) * inv * gg.y + bt.y;
    o4.z = (a.z - mean) * inv * gg.z + bt.z;
    o4.w = (a.w - mean) * inv * gg.w + bt.w;
    *reinterpret_cast<float4*>(dst) = o4;
}

// ---------------------------------------------------------------------------
// Kernel 2: h_V = LN(feat(4) @ W_node + b) * g + beta, 1 warp per node
// ---------------------------------------------------------------------------
__global__ void k_node_out(const float* __restrict__ Wn, const float* __restrict__ bn,
                           const float* __restrict__ gn, const float* __restrict__ bet,
                           float* __restrict__ hV, int N)
{
    int gw   = (blockIdx.x * blockDim.x + threadIdx.x) >> 5;
    int lane = threadIdx.x & 31;
    if (gw >= N) return;
    int c = 4 * lane;
    float4 w0 = *reinterpret_cast<const float4*>(Wn + 0 * 128 + c);
    float4 w1 = *reinterpret_cast<const float4*>(Wn + 1 * 128 + c);
    float4 w2 = *reinterpret_cast<const float4*>(Wn + 2 * 128 + c);
    float4 w3 = *reinterpret_cast<const float4*>(Wn + 3 * 128 + c);
    float4 bb = *reinterpret_cast<const float4*>(bn + c);
    float4 gg = *reinterpret_cast<const float4*>(gn + c);
    float4 bt = *reinterpret_cast<const float4*>(bet + c);

    float4 f = g_nf[gw];
    float4 a;
    a.x = bb.x + f.x * w0.x + f.y * w1.x + f.z * w2.x + f.w * w3.x;
    a.y = bb.y + f.x * w0.y + f.y * w1.y + f.z * w2.y + f.w * w3.y;
    a.z = bb.z + f.x * w0.z + f.y * w1.z + f.z * w2.z + f.w * w3.z;
    a.w = bb.w + f.x * w0.w + f.y * w1.w + f.z * w2.w + f.w * w3.w;
    ln_store(a, gg, bt, hV + (size_t)gw * 128 + c);
}

// ---------------------------------------------------------------------------
// Kernel 3a: per-edge features, ONE THREAD PER EDGE -> g_feat[e][24]
// ---------------------------------------------------------------------------
__global__ void __launch_bounds__(256)
k_edge_feat(const float* __restrict__ X, const int* __restrict__ ei, int E)
{
    int e = blockIdx.x * blockDim.x + threadIdx.x;
    if (e >= E) return;
    int s = __ldg(ei + e);
    int t = __ldg(ei + E + e);

    float4 tb = g_q[t * 3 + 0], tn = g_q[t * 3 + 1], tc = g_q[t * 3 + 2];
    float4 sb = g_q[s * 3 + 0], sn = g_q[s * 3 + 1], sc = g_q[s * 3 + 2];

    float dvx = __ldg(X + 3 * s)     - __ldg(X + 3 * t);
    float dvy = __ldg(X + 3 * s + 1) - __ldg(X + 3 * t + 1);
    float dvz = __ldg(X + 3 * s + 2) - __ldg(X + 3 * t + 2);
    float d2   = dvx * dvx + dvy * dvy + dvz * dvz;
    float dist = sqrtf(d2 + 1e-6f);
    float rinv = 1.0f / fmaxf(sqrtf(d2), 1e-12f);
    float dhx = dvx * rinv, dhy = dvy * rinv, dhz = dvz * rinv;

    float Rxx = tb.x * sb.x + tb.y * sb.y + tb.z * sb.z;
    float Rxy = tb.x * sn.x + tb.y * sn.y + tb.z * sn.z;
    float Rxz = tb.x * sc.x + tb.y * sc.y + tb.z * sc.z;
    float Ryx = tn.x * sb.x + tn.y * sb.y + tn.z * sb.z;
    float Ryy = tn.x * sn.x + tn.y * sn.y + tn.z * sn.z;
    float Ryz = tn.x * sc.x + tn.y * sc.y + tn.z * sc.z;
    float Rzx = tc.x * sb.x + tc.y * sb.y + tc.z * sb.z;
    float Rzy = tc.x * sn.x + tc.y * sn.y + tc.z * sn.z;
    float Rzz = tc.x * sc.x + tc.y * sc.y + tc.z * sc.z;

    float m0 = 0.5f * sqrtf(fabsf(1.0f + Rxx - Ryy - Rzz));
    float m1 = 0.5f * sqrtf(fabsf(1.0f - Rxx + Ryy - Rzz));
    float m2 = 0.5f * sqrtf(fabsf(1.0f - Rxx - Ryy + Rzz));
    float q0 = signf_(Rzy - Ryz) * m0;
    float q1 = signf_(Rxz - Rzx) * m1;
    float q2 = signf_(Ryx - Rxy) * m2;
    float qw = 0.5f * sqrtf(fmaxf(1.0f + Rxx + Ryy + Rzz, 0.0f));
    float qn = sqrtf(q0 * q0 + q1 * q1 + q2 * q2 + qw * qw);
    float vm = (tb.w * sb.w) / fmaxf(qn, 1e-12f);

    float di0 = tb.x * dhx + tb.y * dhy + tb.z * dhz;
    float di1 = tn.x * dhx + tn.y * dhy + tn.z * dhz;
    float di2 = tc.x * dhx + tc.y * dhy + tc.z * dhz;

    float rbf[16];
#pragma unroll
    for (int k = 0; k < 16; k++) {
        float mu = (float)k * (20.0f / 15.0f);
        float tt = (dist - mu) * 0.8f;
        rbf[k] = __expf(-tt * tt);
    }

    float4* fo = g_feat + (size_t)e * 6;
    fo[0] = make_float4(q0 * vm, q1 * vm, q2 * vm, qw * vm);
    fo[1] = make_float4(rbf[0],  rbf[1],  rbf[2],  rbf[3]);
    fo[2] = make_float4(rbf[4],  rbf[5],  rbf[6],  rbf[7]);
    fo[3] = make_float4(rbf[8],  rbf[9],  rbf[10], rbf[11]);
    fo[4] = make_float4(rbf[12], rbf[13], rbf[14], rbf[15]);
    fo[5] = make_float4(di0, di1, di2, 0.0f);
}

// ---------------------------------------------------------------------------
// Kernel 3b: h_E = LN(feat(23) @ W_edge + b) * g + beta
// Warp handles 4 edges/iter; W_edge REGISTER-RESIDENT (23 float4/lane);
// features broadcast via shfl; packed f32x2 FMA accumulation.
// ---------------------------------------------------------------------------
__global__ void __launch_bounds__(128)
k_edge_gemm(const float* __restrict__ We, const float* __restrict__ be,
            const float* __restrict__ ge, const float* __restrict__ bet,
            float* __restrict__ hE, int E)
{
    int tid  = threadIdx.x;
    int lane = tid & 31;
    int gw   = (blockIdx.x * blockDim.x + tid) >> 5;
    int nw   = (gridDim.x * blockDim.x) >> 5;
    int c = 4 * lane;

    // W in registers: 23 float4 per lane (lane owns output cols 4l..4l+3)
    float4 w[23];
#pragma unroll
    for (int k = 0; k < 23; k++)
        w[k] = *reinterpret_cast<const float4*>(We + k * 128 + c);
    float4 bb = *reinterpret_cast<const float4*>(be + c);
    float4 gg = *reinterpret_cast<const float4*>(ge + c);
    float4 bt = *reinterpret_cast<const float4*>(bet + c);
    unsigned long long bias0 = pack2(bb.x, bb.y);
    unsigned long long bias1 = pack2(bb.z, bb.w);

    const float* featf = reinterpret_cast<const float*>(g_feat);

    for (int base = gw * 4; base < E; base += nw * 4) {
        float f[4];
#pragma unroll
        for (int j = 0; j < 4; j++) {
            int e = base + j;
            f[j] = (lane < 24 && e < E) ? featf[(size_t)e * 24 + lane] : 0.0f;
        }

        unsigned long long acc[4][2];
#pragma unroll
        for (int j = 0; j < 4; j++) { acc[j][0] = bias0; acc[j][1] = bias1; }

#pragma unroll
        for (int k = 0; k < 23; k++) {
            ulonglong2 w2;
            w2.x = pack2(w[k].x, w[k].y);
            w2.y = pack2(w[k].z, w[k].w);
#pragma unroll
            for (int j = 0; j < 4; j++) {
                unsigned long long fp = dup2(__shfl_sync(0xffffffffu, f[j], k));
                ffma2(acc[j][0], w2.x, fp);
                ffma2(acc[j][1], w2.y, fp);
            }
        }

#pragma unroll
        for (int j = 0; j < 4; j++) {
            int e = base + j;
            float4 a;
            unpack2(acc[j][0], a.x, a.y);
            unpack2(acc[j][1], a.z, a.w);
            if (e < E)
                ln_store(a, gg, bt, hE + (size_t)e * 128 + c);
        }
    }
}

// ---------------------------------------------------------------------------
extern "C" void kernel_launch(void* const* d_in, const int* in_sizes, int n_in,
                              void* d_out, int out_size)
{
    const float* X    = (const float*)d_in[0];
    const int*   bat  = (const int*)d_in[1];
    const int*   ei   = (const int*)d_in[2];
    const float* Wn   = (const float*)d_in[3];
    const float* bn   = (const float*)d_in[4];
    const float* gn   = (const float*)d_in[5];
    const float* btn  = (const float*)d_in[6];
    const float* We   = (const float*)d_in[7];
    const float* be   = (const float*)d_in[8];
    const float* ge   = (const float*)d_in[9];
    const float* bte  = (const float*)d_in[10];

    int N = in_sizes[0] / 3;
    int E = in_sizes[2] / 2;

    float* hV = (float*)d_out;
    float* hE = hV + (size_t)N * 128;

    k_node_geom<<<(N + 255) / 256, 256>>>(X, bat, N);
    k_node_out<<<(N * 32 + 255) / 256, 256>>>(Wn, bn, gn, btn, hV, N);
    k_edge_feat<<<(E + 255) / 256, 256>>>(X, ei, E);
    // 3 blocks/SM-ish persistent grid so the register-resident W amortizes
    k_edge_gemm<<<1332, 128>>>(We, be, ge, bte, hE, E);
}

// round 5
// speedup vs baseline: 1.2043x; 1.2043x over previous
#include <cuda_runtime.h>
#include <cuda_bf16.h>
#include <math.h>
#include <stdint.h>

#define NMAX 100000
#define EMAX 1000000

// Scratch (module-static, no runtime allocation):
__device__ float4 g_q[NMAX * 3];       // per-node frame (3 cols), valid flag in [0].w
__device__ float4 g_nf[NMAX];          // per-node 4 features
__device__ float4 g_feat[EMAX * 6];    // per-edge 24 floats (23 feats + pad)
__device__ unsigned long long gBfrag[2560]; // precomputed B fragments [s][j][lane]

struct F3 { float x, y, z; };
__device__ __forceinline__ F3 mk3(float a, float b, float c) { F3 r; r.x = a; r.y = b; r.z = c; return r; }
__device__ __forceinline__ F3 sub3(F3 a, F3 b) { return mk3(a.x - b.x, a.y - b.y, a.z - b.z); }
__device__ __forceinline__ float dot3(F3 a, F3 b) { return a.x * b.x + a.y * b.y + a.z * b.z; }
__device__ __forceinline__ F3 cross3(F3 a, F3 b) {
    return mk3(a.y * b.z - a.z * b.y, a.z * b.x - a.x * b.z, a.x * b.y - a.y * b.x);
}
__device__ __forceinline__ F3 nrm3(F3 a) {
    float n = sqrtf(dot3(a, a));
    float s = 1.0f / fmaxf(n, 1e-12f);
    return mk3(a.x * s, a.y * s, a.z * s);
}
__device__ __forceinline__ float signf_(float x) { return (float)((x > 0.0f) - (x < 0.0f)); }

__device__ __forceinline__ uint32_t smem_u32(const void* p) {
    uint32_t a;
    asm("{ .reg .u64 t; cvta.to.shared.u64 t, %1; cvt.u32.u64 %0, t; }" : "=r"(a) : "l"(p));
    return a;
}
__device__ __forceinline__ void mma16816(float* c, uint32_t a0, uint32_t a1, uint32_t a2, uint32_t a3,
                                         uint32_t b0, uint32_t b1) {
    asm volatile(
        "mma.sync.aligned.m16n8k16.row.col.f32.bf16.bf16.f32 "
        "{%0,%1,%2,%3}, {%4,%5,%6,%7}, {%8,%9}, {%0,%1,%2,%3};"
        : "+f"(c[0]), "+f"(c[1]), "+f"(c[2]), "+f"(c[3])
        : "r"(a0), "r"(a1), "r"(a2), "r"(a3), "r"(b0), "r"(b1));
}
__device__ __forceinline__ void ldmatrix_x4(uint32_t& a0, uint32_t& a1, uint32_t& a2, uint32_t& a3, uint32_t addr) {
    asm volatile("ldmatrix.sync.aligned.m8n8.x4.shared.b16 {%0,%1,%2,%3}, [%4];"
                 : "=r"(a0), "=r"(a1), "=r"(a2), "=r"(a3) : "r"(addr));
}
__device__ __forceinline__ float bf16rt(float x) {   // round-trip through bf16
    return __bfloat162float(__float2bfloat16(x));
}

// ---------------------------------------------------------------------------
// Kernel 1: per-node geometry
// ---------------------------------------------------------------------------
__global__ void k_node_geom(const float* __restrict__ X, const int* __restrict__ batch, int N)
{
    int i = blockIdx.x * blockDim.x + threadIdx.x;
    if (i >= N) return;

    auto ldx = [&](int j) -> F3 {
        j = j < 0 ? 0 : (j > N - 1 ? N - 1 : j);
        return mk3(X[3 * j], X[3 * j + 1], X[3 * j + 2]);
    };
    F3 xm1 = ldx(i - 1), x0 = ldx(i), xp1 = ldx(i + 1), xp2 = ldx(i + 2);

    int bi   = (i > 0)     && (batch[i] != batch[i - 1]);
    int bip1 = (i + 1 < N) && (batch[i + 1] != batch[i]);
    int bip2 = (i + 2 < N) && (batch[i + 2] != batch[i + 1]);
    bool bad_a = bi || bip1 || (i == 0) || (i == N - 1);
    bool bad_d = bi || bip1 || bip2 || (i == 0) || (i >= N - 2);

    F3 Um = nrm3(sub3(x0,  xm1));
    F3 Uc = nrm3(sub3(xp1, x0));
    F3 Up = nrm3(sub3(xp2, xp1));

    F3 c1 = nrm3(cross3(Um, Uc));
    F3 c2 = nrm3(cross3(Uc, Up));
    float cosd = fminf(fmaxf(dot3(c1, c2), -1.0f + 1e-6f), 1.0f - 1e-6f);
    float sg = signf_(dot3(c2, Um));
    float sdih = sg * sqrtf(fmaxf(1.0f - cosd * cosd, 0.0f));
    float cdih = (sg == 0.0f) ? 1.0f : cosd;

    F3 d0 = nrm3(sub3(xm1, x0));
    F3 d1 = nrm3(sub3(xp1, x0));
    float cosa = dot3(d0, d1);
    float sina = sqrtf(1.0f - cosa * cosa + 1e-6f);

    float4 nf;
    nf.x = bad_d ? 0.0f : sdih;
    nf.y = bad_d ? 0.0f : cdih;
    nf.z = bad_a ? 0.0f : sina;
    nf.w = bad_a ? 0.0f : cosa;
    g_nf[i] = nf;

    F3 bv = nrm3(sub3(Um, Uc));
    F3 nv = nrm3(cross3(Um, Uc));
    F3 cv = cross3(bv, nv);
    float m = bad_a ? 0.0f : 1.0f;
    g_q[i * 3 + 0] = make_float4(bv.x * m, bv.y * m, bv.z * m, m);
    g_q[i * 3 + 1] = make_float4(nv.x * m, nv.y * m, nv.z * m, 0.0f);
    g_q[i * 3 + 2] = make_float4(cv.x * m, cv.y * m, cv.z * m, 0.0f);
}

// ---------------------------------------------------------------------------
// Warp LayerNorm helper (node path)
// ---------------------------------------------------------------------------
__device__ __forceinline__ void ln_store(float4 a, float4 gg, float4 bt, float* __restrict__ dst)
{
    float s1 = a.x + a.y + a.z + a.w;
    float s2 = a.x * a.x + a.y * a.y + a.z * a.z + a.w * a.w;
#pragma unroll
    for (int o = 16; o > 0; o >>= 1) {
        s1 += __shfl_xor_sync(0xffffffffu, s1, o);
        s2 += __shfl_xor_sync(0xffffffffu, s2, o);
    }
    float mean = s1 * (1.0f / 128.0f);
    float var  = fmaxf(s2 * (1.0f / 128.0f) - mean * mean, 0.0f);
    float inv  = rsqrtf(var + 1e-5f);
    float4 o4;
    o4.x = (a.x - mean) * inv * gg.x + bt.x;
    o4.y = (a.y - mean) * inv * gg.y + bt.y;
    o4.z = (a.z - mean) * inv * gg.z + bt.z;
    o4.w = (a.w - mean) * inv * gg.w + bt.w;
    *reinterpret_cast<float4*>(dst) = o4;
}

// ---------------------------------------------------------------------------
// Kernel 2: h_V, 1 warp per node
// ---------------------------------------------------------------------------
__global__ void k_node_out(const float* __restrict__ Wn, const float* __restrict__ bn,
                           const float* __restrict__ gn, const float* __restrict__ bet,
                           float* __restrict__ hV, int N)
{
    int gw   = (blockIdx.x * blockDim.x + threadIdx.x) >> 5;
    int lane = threadIdx.x & 31;
    if (gw >= N) return;
    int c = 4 * lane;
    float4 w0 = *reinterpret_cast<const float4*>(Wn + 0 * 128 + c);
    float4 w1 = *reinterpret_cast<const float4*>(Wn + 1 * 128 + c);
    float4 w2 = *reinterpret_cast<const float4*>(Wn + 2 * 128 + c);
    float4 w3 = *reinterpret_cast<const float4*>(Wn + 3 * 128 + c);
    float4 bb = *reinterpret_cast<const float4*>(bn + c);
    float4 gg = *reinterpret_cast<const float4*>(gn + c);
    float4 bt = *reinterpret_cast<const float4*>(bet + c);

    float4 f = g_nf[gw];
    float4 a;
    a.x = bb.x + f.x * w0.x + f.y * w1.x + f.z * w2.x + f.w * w3.x;
    a.y = bb.y + f.x * w0.y + f.y * w1.y + f.z * w2.y + f.w * w3.y;
    a.z = bb.z + f.x * w0.z + f.y * w1.z + f.z * w2.z + f.w * w3.z;
    a.w = bb.w + f.x * w0.w + f.y * w1.w + f.z * w2.w + f.w * w3.w;
    ln_store(a, gg, bt, hV + (size_t)gw * 128 + c);
}

// ---------------------------------------------------------------------------
// Kernel 3a: per-edge features, one thread per edge -> g_feat[e][24]
// ---------------------------------------------------------------------------
__global__ void __launch_bounds__(256)
k_edge_feat(const float* __restrict__ X, const int* __restrict__ ei, int E)
{
    int e = blockIdx.x * blockDim.x + threadIdx.x;
    if (e >= E) return;
    int s = __ldg(ei + e);
    int t = __ldg(ei + E + e);

    float4 tb = g_q[t * 3 + 0], tn = g_q[t * 3 + 1], tc = g_q[t * 3 + 2];
    float4 sb = g_q[s * 3 + 0], sn = g_q[s * 3 + 1], sc = g_q[s * 3 + 2];

    float dvx = __ldg(X + 3 * s)     - __ldg(X + 3 * t);
    float dvy = __ldg(X + 3 * s + 1) - __ldg(X + 3 * t + 1);
    float dvz = __ldg(X + 3 * s + 2) - __ldg(X + 3 * t + 2);
    float d2   = dvx * dvx + dvy * dvy + dvz * dvz;
    float dist = sqrtf(d2 + 1e-6f);
    float rinv = 1.0f / fmaxf(sqrtf(d2), 1e-12f);
    float dhx = dvx * rinv, dhy = dvy * rinv, dhz = dvz * rinv;

    float Rxx = tb.x * sb.x + tb.y * sb.y + tb.z * sb.z;
    float Rxy = tb.x * sn.x + tb.y * sn.y + tb.z * sn.z;
    float Rxz = tb.x * sc.x + tb.y * sc.y + tb.z * sc.z;
    float Ryx = tn.x * sb.x + tn.y * sb.y + tn.z * sb.z;
    float Ryy = tn.x * sn.x + tn.y * sn.y + tn.z * sn.z;
    float Ryz = tn.x * sc.x + tn.y * sc.y + tn.z * sc.z;
    float Rzx = tc.x * sb.x + tc.y * sb.y + tc.z * sb.z;
    float Rzy = tc.x * sn.x + tc.y * sn.y + tc.z * sn.z;
    float Rzz = tc.x * sc.x + tc.y * sc.y + tc.z * sc.z;

    float m0 = 0.5f * sqrtf(fabsf(1.0f + Rxx - Ryy - Rzz));
    float m1 = 0.5f * sqrtf(fabsf(1.0f - Rxx + Ryy - Rzz));
    float m2 = 0.5f * sqrtf(fabsf(1.0f - Rxx - Ryy + Rzz));
    float q0 = signf_(Rzy - Ryz) * m0;
    float q1 = signf_(Rxz - Rzx) * m1;
    float q2 = signf_(Ryx - Rxy) * m2;
    float qw = 0.5f * sqrtf(fmaxf(1.0f + Rxx + Ryy + Rzz, 0.0f));
    float qn = sqrtf(q0 * q0 + q1 * q1 + q2 * q2 + qw * qw);
    float vm = (tb.w * sb.w) / fmaxf(qn, 1e-12f);

    float di0 = tb.x * dhx + tb.y * dhy + tb.z * dhz;
    float di1 = tn.x * dhx + tn.y * dhy + tn.z * dhz;
    float di2 = tc.x * dhx + tc.y * dhy + tc.z * dhz;

    float rbf[16];
#pragma unroll
    for (int k = 0; k < 16; k++) {
        float mu = (float)k * (20.0f / 15.0f);
        float tt = (dist - mu) * 0.8f;
        rbf[k] = __expf(-tt * tt);
    }

    float4* fo = g_feat + (size_t)e * 6;
    fo[0] = make_float4(q0 * vm, q1 * vm, q2 * vm, qw * vm);
    fo[1] = make_float4(rbf[0],  rbf[1],  rbf[2],  rbf[3]);
    fo[2] = make_float4(rbf[4],  rbf[5],  rbf[6],  rbf[7]);
    fo[3] = make_float4(rbf[8],  rbf[9],  rbf[10], rbf[11]);
    fo[4] = make_float4(rbf[12], rbf[13], rbf[14], rbf[15]);
    fo[5] = make_float4(di0, di1, di2, 0.0f);
}

// ---------------------------------------------------------------------------
// Kernel 3b-prep: B fragments for mma.m16n8k16 (run once, tiny).
// W' (K'=80 x 128): rows 0..22=hi(W), 23..45=lo(W), 46..68=hi(W),
// 69=hi(bias), 70=lo(bias), 71..79=0.
// A' cols: 0..22=hi(f), 23..45=hi(f), 46..68=lo(f), 69..70=1  =>
// A'B' = hi.Whi + hi.Wlo + lo.Whi + bias   (drops lo.lo ~ 2^-18)
// frag [s][j][lane]: b0 = pack(W'[16s+2t][8j+g], W'[16s+2t+1][..]),
//                    b1 = same at k+8   (g=lane>>2, t=lane&3)
// ---------------------------------------------------------------------------
__global__ void k_prep_Bfrag(const float* __restrict__ We, const float* __restrict__ be)
{
    int idx = blockIdx.x * blockDim.x + threadIdx.x;
    if (idx >= 2560) return;
    int lane = idx & 31, j = (idx >> 5) & 15, s = idx >> 9;
    int gid = lane >> 2, tig = lane & 3, n = 8 * j + gid;

    auto wv = [&](int r) -> float {
        if (r < 23)  return bf16rt(We[r * 128 + n]);
        if (r < 46)  { float x = We[(r - 23) * 128 + n]; return x - bf16rt(x); }
        if (r < 69)  return bf16rt(We[(r - 46) * 128 + n]);
        if (r == 69) return bf16rt(be[n]);
        if (r == 70) { float x = be[n]; return x - bf16rt(x); }
        return 0.0f;
    };
    int k0 = 16 * s + 2 * tig;
    __nv_bfloat162 p0 = __floats2bfloat162_rn(wv(k0),     wv(k0 + 1));
    __nv_bfloat162 p1 = __floats2bfloat162_rn(wv(k0 + 8), wv(k0 + 9));
    uint32_t b0 = *reinterpret_cast<uint32_t*>(&p0);
    uint32_t b1 = *reinterpret_cast<uint32_t*>(&p1);
    gBfrag[idx] = ((unsigned long long)b1 << 32) | b0;
}

// ---------------------------------------------------------------------------
// Kernel 3b: tensor-core edge GEMM + LN.  Block = 128 thr = 4 warps.
// Tile = 16 edges x 128 cols; warp w owns cols 32w..32w+31 (4 n-tiles).
// ---------------------------------------------------------------------------
__global__ void __launch_bounds__(128, 4)
k_edge_mma(const float* __restrict__ ge, const float* __restrict__ bet,
           float* __restrict__ hE, int E, int ntiles)
{
    __shared__ float fS[16 * 24];
    __shared__ __nv_bfloat16 A_img[16 * 88];   // stride 88 bf16 = conflict-free ldmatrix
    __shared__ float2 red[16][4];
    __shared__ float2 mi[16];

    int tid = threadIdx.x, w = tid >> 5, lane = tid & 31;
    int gid = lane >> 2, tig = lane & 3;

    // B fragments: 40 regs/lane
    uint32_t B0[5][4], B1[5][4];
#pragma unroll
    for (int s = 0; s < 5; s++)
#pragma unroll
        for (int jj = 0; jj < 4; jj++) {
            unsigned long long v = gBfrag[(s * 16 + (w * 4 + jj)) * 32 + lane];
            B0[s][jj] = (uint32_t)v;
            B1[s][jj] = (uint32_t)(v >> 32);
        }
    float2 gg2[4], bt2[4];
#pragma unroll
    for (int jj = 0; jj < 4; jj++) {
        int colb = 32 * w + 8 * jj + 2 * tig;
        gg2[jj] = *reinterpret_cast<const float2*>(ge + colb);
        bt2[jj] = *reinterpret_cast<const float2*>(bet + colb);
    }
    uint32_t aAddr = smem_u32(A_img)
                   + ((lane & 7) + ((lane & 8) ? 8 : 0)) * 176
                   + ((lane & 16) ? 16 : 0);

    for (int tile = blockIdx.x; tile < ntiles; tile += gridDim.x) {
        int base = tile * 16;

        // stage raw features (coalesced)
        if (tid < 96) {
            int e = base + tid / 6;
            float4 v = (e < E) ? g_feat[(size_t)base * 6 + tid] : make_float4(0.f, 0.f, 0.f, 0.f);
            reinterpret_cast<float4*>(fS)[tid] = v;
        }
        __syncthreads();

        // build bf16 A image: 8 threads per edge, 8 items each
        {
            int e = tid >> 3, p = tid & 7;
            const float* fe = fS + e * 24;
            __nv_bfloat16* Ae = A_img + e * 88;
#pragma unroll
            for (int u = 0; u < 8; u++) {
                int i = p + 8 * u;
                if (i < 23) {
                    __nv_bfloat16 h = __float2bfloat16(fe[i]);
                    Ae[i] = h;
                    Ae[i + 23] = h;
                } else if (i < 46) {
                    float x = fe[i - 23];
                    Ae[i + 23] = __float2bfloat16(x - bf16rt(x));
                } else {
                    int c = i + 23;  // 69..86
                    Ae[c] = __float2bfloat16((c == 69 || c == 70) ? 1.0f : 0.0f);
                }
            }
        }
        __syncthreads();

        // MMA: 5 k-steps x 4 n-tiles
        float C[4][4];
#pragma unroll
        for (int jj = 0; jj < 4; jj++)
#pragma unroll
            for (int q = 0; q < 4; q++) C[jj][q] = 0.0f;
#pragma unroll
        for (int s = 0; s < 5; s++) {
            uint32_t a0, a1, a2, a3;
            ldmatrix_x4(a0, a1, a2, a3, aAddr + s * 32);
#pragma unroll
            for (int jj = 0; jj < 4; jj++)
                mma16816(C[jj], a0, a1, a2, a3, B0[s][jj], B1[s][jj]);
        }

        // LN partials: rows gid (A) and gid+8 (B), warp's 32 cols
        float s1A = 0.f, s2A = 0.f, s1B = 0.f, s2B = 0.f;
#pragma unroll
        for (int jj = 0; jj < 4; jj++) {
            s1A += C[jj][0] + C[jj][1];
            s2A += C[jj][0] * C[jj][0] + C[jj][1] * C[jj][1];
            s1B += C[jj][2] + C[jj][3];
            s2B += C[jj][2] * C[jj][2] + C[jj][3] * C[jj][3];
        }
#pragma unroll
        for (int o = 1; o <= 2; o <<= 1) {
            s1A += __shfl_xor_sync(0xffffffffu, s1A, o);
            s2A += __shfl_xor_sync(0xffffffffu, s2A, o);
            s1B += __shfl_xor_sync(0xffffffffu, s1B, o);
            s2B += __shfl_xor_sync(0xffffffffu, s2B, o);
        }
        if (tig == 0) {
            red[gid][w]     = make_float2(s1A, s2A);
            red[gid + 8][w] = make_float2(s1B, s2B);
        }
        __syncthreads();
        if (tid < 16) {
            float s1 = 0.f, s2 = 0.f;
#pragma unroll
            for (int ww = 0; ww < 4; ww++) {
                float2 v = red[tid][ww];
                s1 += v.x; s2 += v.y;
            }
            float mean = s1 * (1.0f / 128.0f);
            float var  = fmaxf(s2 * (1.0f / 128.0f) - mean * mean, 0.0f);
            mi[tid] = make_float2(mean, rsqrtf(var + 1e-5f));
        }
        __syncthreads();

        float2 miA = mi[gid], miB = mi[gid + 8];
        int eA = base + gid, eB = eA + 8;
#pragma unroll
        for (int jj = 0; jj < 4; jj++) {
            int colb = 32 * w + 8 * jj + 2 * tig;
            if (eA < E) {
                float2 o;
                o.x = (C[jj][0] - miA.x) * miA.y * gg2[jj].x + bt2[jj].x;
                o.y = (C[jj][1] - miA.x) * miA.y * gg2[jj].y + bt2[jj].y;
                *reinterpret_cast<float2*>(hE + (size_t)eA * 128 + colb) = o;
            }
            if (eB < E) {
                float2 o;
                o.x = (C[jj][2] - miB.x) * miB.y * gg2[jj].x + bt2[jj].x;
                o.y = (C[jj][3] - miB.x) * miB.y * gg2[jj].y + bt2[jj].y;
                *reinterpret_cast<float2*>(hE + (size_t)eB * 128 + colb) = o;
            }
        }
    }
}

// ---------------------------------------------------------------------------
extern "C" void kernel_launch(void* const* d_in, const int* in_sizes, int n_in,
                              void* d_out, int out_size)
{
    const float* X    = (const float*)d_in[0];
    const int*   bat  = (const int*)d_in[1];
    const int*   ei   = (const int*)d_in[2];
    const float* Wn   = (const float*)d_in[3];
    const float* bn   = (const float*)d_in[4];
    const float* gn   = (const float*)d_in[5];
    const float* btn  = (const float*)d_in[6];
    const float* We   = (const float*)d_in[7];
    const float* be   = (const float*)d_in[8];
    const float* ge   = (const float*)d_in[9];
    const float* bte  = (const float*)d_in[10];

    int N = in_sizes[0] / 3;
    int E = in_sizes[2] / 2;
    int ntiles = (E + 15) / 16;

    float* hV = (float*)d_out;
    float* hE = hV + (size_t)N * 128;

    k_prep_Bfrag<<<5, 512>>>(We, be);
    k_node_geom<<<(N + 255) / 256, 256>>>(X, bat, N);
    k_node_out<<<(N * 32 + 255) / 256, 256>>>(Wn, bn, gn, btn, hV, N);
    k_edge_feat<<<(E + 255) / 256, 256>>>(X, ei, E);
    k_edge_mma<<<1480, 128>>>(ge, bte, hE, E, ntiles);
}

// round 6
// speedup vs baseline: 1.8388x; 1.5268x over previous
#include <cuda_runtime.h>
#include <cuda_bf16.h>
#include <math.h>
#include <stdint.h>

#define NMAX 100000

// Scratch (module-static, no runtime allocation):
__device__ float4 g_q[NMAX * 3];       // per-node frame (3 cols), valid flag in [0].w
__device__ float4 g_nf[NMAX];          // per-node 4 features
__device__ unsigned long long gBfrag[2560]; // precomputed B fragments [s][j][lane]

struct F3 { float x, y, z; };
__device__ __forceinline__ F3 mk3(float a, float b, float c) { F3 r; r.x = a; r.y = b; r.z = c; return r; }
__device__ __forceinline__ F3 sub3(F3 a, F3 b) { return mk3(a.x - b.x, a.y - b.y, a.z - b.z); }
__device__ __forceinline__ float dot3(F3 a, F3 b) { return a.x * b.x + a.y * b.y + a.z * b.z; }
__device__ __forceinline__ F3 cross3(F3 a, F3 b) {
    return mk3(a.y * b.z - a.z * b.y, a.z * b.x - a.x * b.z, a.x * b.y - a.y * b.x);
}
__device__ __forceinline__ F3 nrm3(F3 a) {
    float n = sqrtf(dot3(a, a));
    float s = 1.0f / fmaxf(n, 1e-12f);
    return mk3(a.x * s, a.y * s, a.z * s);
}
__device__ __forceinline__ float signf_(float x) { return (float)((x > 0.0f) - (x < 0.0f)); }

__device__ __forceinline__ uint32_t smem_u32(const void* p) {
    uint32_t a;
    asm("{ .reg .u64 t; cvta.to.shared.u64 t, %1; cvt.u32.u64 %0, t; }" : "=r"(a) : "l"(p));
    return a;
}
__device__ __forceinline__ void mma16816(float* c, uint32_t a0, uint32_t a1, uint32_t a2, uint32_t a3,
                                         uint32_t b0, uint32_t b1) {
    asm volatile(
        "mma.sync.aligned.m16n8k16.row.col.f32.bf16.bf16.f32 "
        "{%0,%1,%2,%3}, {%4,%5,%6,%7}, {%8,%9}, {%0,%1,%2,%3};"
        : "+f"(c[0]), "+f"(c[1]), "+f"(c[2]), "+f"(c[3])
        : "r"(a0), "r"(a1), "r"(a2), "r"(a3), "r"(b0), "r"(b1));
}
__device__ __forceinline__ void ldmatrix_x4(uint32_t& a0, uint32_t& a1, uint32_t& a2, uint32_t& a3, uint32_t addr) {
    asm volatile("ldmatrix.sync.aligned.m8n8.x4.shared.b16 {%0,%1,%2,%3}, [%4];"
                 : "=r"(a0), "=r"(a1), "=r"(a2), "=r"(a3) : "r"(addr));
}
__device__ __forceinline__ float bf16rt(float x) {
    return __bfloat162float(__float2bfloat16(x));
}

// ---------------------------------------------------------------------------
// Kernel 1: per-node geometry
// ---------------------------------------------------------------------------
__global__ void k_node_geom(const float* __restrict__ X, const int* __restrict__ batch, int N)
{
    int i = blockIdx.x * blockDim.x + threadIdx.x;
    if (i >= N) return;

    auto ldx = [&](int j) -> F3 {
        j = j < 0 ? 0 : (j > N - 1 ? N - 1 : j);
        return mk3(X[3 * j], X[3 * j + 1], X[3 * j + 2]);
    };
    F3 xm1 = ldx(i - 1), x0 = ldx(i), xp1 = ldx(i + 1), xp2 = ldx(i + 2);

    int bi   = (i > 0)     && (batch[i] != batch[i - 1]);
    int bip1 = (i + 1 < N) && (batch[i + 1] != batch[i]);
    int bip2 = (i + 2 < N) && (batch[i + 2] != batch[i + 1]);
    bool bad_a = bi || bip1 || (i == 0) || (i == N - 1);
    bool bad_d = bi || bip1 || bip2 || (i == 0) || (i >= N - 2);

    F3 Um = nrm3(sub3(x0,  xm1));
    F3 Uc = nrm3(sub3(xp1, x0));
    F3 Up = nrm3(sub3(xp2, xp1));

    F3 c1 = nrm3(cross3(Um, Uc));
    F3 c2 = nrm3(cross3(Uc, Up));
    float cosd = fminf(fmaxf(dot3(c1, c2), -1.0f + 1e-6f), 1.0f - 1e-6f);
    float sg = signf_(dot3(c2, Um));
    float sdih = sg * sqrtf(fmaxf(1.0f - cosd * cosd, 0.0f));
    float cdih = (sg == 0.0f) ? 1.0f : cosd;

    F3 d0 = nrm3(sub3(xm1, x0));
    F3 d1 = nrm3(sub3(xp1, x0));
    float cosa = dot3(d0, d1);
    float sina = sqrtf(1.0f - cosa * cosa + 1e-6f);

    float4 nf;
    nf.x = bad_d ? 0.0f : sdih;
    nf.y = bad_d ? 0.0f : cdih;
    nf.z = bad_a ? 0.0f : sina;
    nf.w = bad_a ? 0.0f : cosa;
    g_nf[i] = nf;

    F3 bv = nrm3(sub3(Um, Uc));
    F3 nv = nrm3(cross3(Um, Uc));
    F3 cv = cross3(bv, nv);
    float m = bad_a ? 0.0f : 1.0f;
    g_q[i * 3 + 0] = make_float4(bv.x * m, bv.y * m, bv.z * m, m);
    g_q[i * 3 + 1] = make_float4(nv.x * m, nv.y * m, nv.z * m, 0.0f);
    g_q[i * 3 + 2] = make_float4(cv.x * m, cv.y * m, cv.z * m, 0.0f);
}

// ---------------------------------------------------------------------------
// Warp LayerNorm helper (node path)
// ---------------------------------------------------------------------------
__device__ __forceinline__ void ln_store(float4 a, float4 gg, float4 bt, float* __restrict__ dst)
{
    float s1 = a.x + a.y + a.z + a.w;
    float s2 = a.x * a.x + a.y * a.y + a.z * a.z + a.w * a.w;
#pragma unroll
    for (int o = 16; o > 0; o >>= 1) {
        s1 += __shfl_xor_sync(0xffffffffu, s1, o);
        s2 += __shfl_xor_sync(0xffffffffu, s2, o);
    }
    float mean = s1 * (1.0f / 128.0f);
    float var  = fmaxf(s2 * (1.0f / 128.0f) - mean * mean, 0.0f);
    float inv  = rsqrtf(var + 1e-5f);
    float4 o4;
    o4.x = (a.x - mean) * inv * gg.x + bt.x;
    o4.y = (a.y - mean) * inv * gg.y + bt.y;
    o4.z = (a.z - mean) * inv * gg.z + bt.z;
    o4.w = (a.w - mean) * inv * gg.w + bt.w;
    *reinterpret_cast<float4*>(dst) = o4;
}

// ---------------------------------------------------------------------------
// Kernel 2: h_V, 1 warp per node
// ---------------------------------------------------------------------------
__global__ void k_node_out(const float* __restrict__ Wn, const float* __restrict__ bn,
                           const float* __restrict__ gn, const float* __restrict__ bet,
                           float* __restrict__ hV, int N)
{
    int gw   = (blockIdx.x * blockDim.x + threadIdx.x) >> 5;
    int lane = threadIdx.x & 31;
    if (gw >= N) return;
    int c = 4 * lane;
    float4 w0 = *reinterpret_cast<const float4*>(Wn + 0 * 128 + c);
    float4 w1 = *reinterpret_cast<const float4*>(Wn + 1 * 128 + c);
    float4 w2 = *reinterpret_cast<const float4*>(Wn + 2 * 128 + c);
    float4 w3 = *reinterpret_cast<const float4*>(Wn + 3 * 128 + c);
    float4 bb = *reinterpret_cast<const float4*>(bn + c);
    float4 gg = *reinterpret_cast<const float4*>(gn + c);
    float4 bt = *reinterpret_cast<const float4*>(bet + c);

    float4 f = g_nf[gw];
    float4 a;
    a.x = bb.x + f.x * w0.x + f.y * w1.x + f.z * w2.x + f.w * w3.x;
    a.y = bb.y + f.x * w0.y + f.y * w1.y + f.z * w2.y + f.w * w3.y;
    a.z = bb.z + f.x * w0.z + f.y * w1.z + f.z * w2.z + f.w * w3.z;
    a.w = bb.w + f.x * w0.w + f.y * w1.w + f.z * w2.w + f.w * w3.w;
    ln_store(a, gg, bt, hV + (size_t)gw * 128 + c);
}

// ---------------------------------------------------------------------------
// Kernel 3-prep: B fragments for mma.m16n8k16 (run once, tiny).
// W' (K'=80 x 128): rows 0..22=hi(W), 23..45=lo(W), 46..68=hi(W),
// 69=hi(bias), 70=lo(bias), 71..79=0.
// A' cols: 0..22=hi(f), 23..45=hi(f), 46..68=lo(f), 69..70=1  =>
// A'B' = hi.Whi + hi.Wlo + lo.Whi + bias   (drops lo.lo ~ 2^-18)
// ---------------------------------------------------------------------------
__global__ void k_prep_Bfrag(const float* __restrict__ We, const float* __restrict__ be)
{
    int idx = blockIdx.x * blockDim.x + threadIdx.x;
    if (idx >= 2560) return;
    int lane = idx & 31, j = (idx >> 5) & 15, s = idx >> 9;
    int gid = lane >> 2, tig = lane & 3, n = 8 * j + gid;

    auto wv = [&](int r) -> float {
        if (r < 23)  return bf16rt(We[r * 128 + n]);
        if (r < 46)  { float x = We[(r - 23) * 128 + n]; return x - bf16rt(x); }
        if (r < 69)  return bf16rt(We[(r - 46) * 128 + n]);
        if (r == 69) return bf16rt(be[n]);
        if (r == 70) { float x = be[n]; return x - bf16rt(x); }
        return 0.0f;
    };
    int k0 = 16 * s + 2 * tig;
    __nv_bfloat162 p0 = __floats2bfloat162_rn(wv(k0),     wv(k0 + 1));
    __nv_bfloat162 p1 = __floats2bfloat162_rn(wv(k0 + 8), wv(k0 + 9));
    uint32_t b0 = *reinterpret_cast<uint32_t*>(&p0);
    uint32_t b1 = *reinterpret_cast<uint32_t*>(&p1);
    gBfrag[idx] = ((unsigned long long)b1 << 32) | b0;
}

// ---------------------------------------------------------------------------
// Kernel 3: FUSED edge features + tensor-core GEMM + LN.
// Block = 128 threads = 4 warps; tile = 128 edges.
// Phase 1: thread e computes its edge's 23 features, writes bf16 A image
//          (hi | hi | lo | 1 1 | 0-pad = 88 cols, stride 88 bf16) to smem.
// Phase 2: 8 row-groups of 16 edges: ldmatrix + mma (B frags in regs),
//          cross-warp LN reduce, coalesced-ish float2 stores.
// ---------------------------------------------------------------------------
__global__ void __launch_bounds__(128)
k_edge_fused(const float* __restrict__ X, const int* __restrict__ ei, int E,
             const float* __restrict__ ge, const float* __restrict__ bet,
             float* __restrict__ hE)
{
    __shared__ __nv_bfloat16 A_img[128 * 88];
    __shared__ float2 red[16][4];
    __shared__ float2 mi[16];

    int tid = threadIdx.x, w = tid >> 5, lane = tid & 31;
    int gid = lane >> 2, tig = lane & 3;
    int base = blockIdx.x * 128;

    // ---- B fragments: 40 regs/lane; LN params ----
    uint32_t B0[5][4], B1[5][4];
#pragma unroll
    for (int s = 0; s < 5; s++)
#pragma unroll
        for (int jj = 0; jj < 4; jj++) {
            unsigned long long v = gBfrag[(s * 16 + (w * 4 + jj)) * 32 + lane];
            B0[s][jj] = (uint32_t)v;
            B1[s][jj] = (uint32_t)(v >> 32);
        }
    float2 gg2[4], bt2[4];
#pragma unroll
    for (int jj = 0; jj < 4; jj++) {
        int colb = 32 * w + 8 * jj + 2 * tig;
        gg2[jj] = *reinterpret_cast<const float2*>(ge + colb);
        bt2[jj] = *reinterpret_cast<const float2*>(bet + colb);
    }

    // ---- Phase 1: per-thread edge features -> A image ----
    {
        int e = base + tid;
        float f[23];
#pragma unroll
        for (int k = 0; k < 23; k++) f[k] = 0.0f;
        if (e < E) {
            int s = __ldg(ei + e);
            int t = __ldg(ei + E + e);

            float4 tb = g_q[t * 3 + 0], tn = g_q[t * 3 + 1], tc = g_q[t * 3 + 2];
            float4 sb = g_q[s * 3 + 0], sn = g_q[s * 3 + 1], sc = g_q[s * 3 + 2];

            float dvx = __ldg(X + 3 * s)     - __ldg(X + 3 * t);
            float dvy = __ldg(X + 3 * s + 1) - __ldg(X + 3 * t + 1);
            float dvz = __ldg(X + 3 * s + 2) - __ldg(X + 3 * t + 2);
            float d2   = dvx * dvx + dvy * dvy + dvz * dvz;
            float dist = sqrtf(d2 + 1e-6f);
            float rinv = 1.0f / fmaxf(sqrtf(d2), 1e-12f);
            float dhx = dvx * rinv, dhy = dvy * rinv, dhz = dvz * rinv;

            float Rxx = tb.x * sb.x + tb.y * sb.y + tb.z * sb.z;
            float Rxy = tb.x * sn.x + tb.y * sn.y + tb.z * sn.z;
            float Rxz = tb.x * sc.x + tb.y * sc.y + tb.z * sc.z;
            float Ryx = tn.x * sb.x + tn.y * sb.y + tn.z * sb.z;
            float Ryy = tn.x * sn.x + tn.y * sn.y + tn.z * sn.z;
            float Ryz = tn.x * sc.x + tn.y * sc.y + tn.z * sc.z;
            float Rzx = tc.x * sb.x + tc.y * sb.y + tc.z * sb.z;
            float Rzy = tc.x * sn.x + tc.y * sn.y + tc.z * sn.z;
            float Rzz = tc.x * sc.x + tc.y * sc.y + tc.z * sc.z;

            float m0 = 0.5f * sqrtf(fabsf(1.0f + Rxx - Ryy - Rzz));
            float m1 = 0.5f * sqrtf(fabsf(1.0f - Rxx + Ryy - Rzz));
            float m2 = 0.5f * sqrtf(fabsf(1.0f - Rxx - Ryy + Rzz));
            float q0 = signf_(Rzy - Ryz) * m0;
            float q1 = signf_(Rxz - Rzx) * m1;
            float q2 = signf_(Ryx - Rxy) * m2;
            float qw = 0.5f * sqrtf(fmaxf(1.0f + Rxx + Ryy + Rzz, 0.0f));
            float qn = sqrtf(q0 * q0 + q1 * q1 + q2 * q2 + qw * qw);
            float vm = (tb.w * sb.w) / fmaxf(qn, 1e-12f);

            f[0] = q0 * vm; f[1] = q1 * vm; f[2] = q2 * vm; f[3] = qw * vm;
#pragma unroll
            for (int k = 0; k < 16; k++) {
                float mu = (float)k * (20.0f / 15.0f);
                float tt = (dist - mu) * 0.8f;
                f[4 + k] = __expf(-tt * tt);
            }
            f[20] = tb.x * dhx + tb.y * dhy + tb.z * dhz;
            f[21] = tn.x * dhx + tn.y * dhy + tn.z * dhz;
            f[22] = tc.x * dhx + tc.y * dhy + tc.z * dhz;
        }

        uint32_t* Au = reinterpret_cast<uint32_t*>(A_img) + tid * 44;
#pragma unroll
        for (int i = 0; i < 44; i++) {
            int c0 = 2 * i, c1 = 2 * i + 1;
            float a0, a1;
            // col c: 0..22 hi(f[c]); 23..45 hi(f[c-23]); 46..68 lo(f[c-46]); 69,70 = 1; else 0
            a0 = (c0 < 23) ? bf16rt(f[c0])
               : (c0 < 46) ? bf16rt(f[c0 - 23])
               : (c0 < 69) ? (f[c0 - 46] - bf16rt(f[c0 - 46]))
               : (c0 < 71) ? 1.0f : 0.0f;
            a1 = (c1 < 23) ? bf16rt(f[c1])
               : (c1 < 46) ? bf16rt(f[c1 - 23])
               : (c1 < 69) ? (f[c1 - 46] - bf16rt(f[c1 - 46]))
               : (c1 < 71) ? 1.0f : 0.0f;
            __nv_bfloat162 p = __floats2bfloat162_rn(a0, a1);
            Au[i] = *reinterpret_cast<uint32_t*>(&p);
        }
    }
    __syncthreads();

    // ---- Phase 2: 8 row-groups of 16 edges ----
    uint32_t aBase = smem_u32(A_img)
                   + ((lane & 7) + ((lane & 8) ? 8 : 0)) * 176
                   + ((lane & 16) ? 16 : 0);

#pragma unroll 1
    for (int rg = 0; rg < 8; rg++) {
        float C[4][4];
#pragma unroll
        for (int jj = 0; jj < 4; jj++)
#pragma unroll
            for (int q = 0; q < 4; q++) C[jj][q] = 0.0f;

        uint32_t aAddr = aBase + rg * (16 * 176);
#pragma unroll
        for (int s = 0; s < 5; s++) {
            uint32_t a0, a1, a2, a3;
            ldmatrix_x4(a0, a1, a2, a3, aAddr + s * 32);
#pragma unroll
            for (int jj = 0; jj < 4; jj++)
                mma16816(C[jj], a0, a1, a2, a3, B0[s][jj], B1[s][jj]);
        }

        // LN partials for rows gid / gid+8 of this row-group (warp's 32 cols)
        float s1A = 0.f, s2A = 0.f, s1B = 0.f, s2B = 0.f;
#pragma unroll
        for (int jj = 0; jj < 4; jj++) {
            s1A += C[jj][0] + C[jj][1];
            s2A += C[jj][0] * C[jj][0] + C[jj][1] * C[jj][1];
            s1B += C[jj][2] + C[jj][3];
            s2B += C[jj][2] * C[jj][2] + C[jj][3] * C[jj][3];
        }
#pragma unroll
        for (int o = 1; o <= 2; o <<= 1) {
            s1A += __shfl_xor_sync(0xffffffffu, s1A, o);
            s2A += __shfl_xor_sync(0xffffffffu, s2A, o);
            s1B += __shfl_xor_sync(0xffffffffu, s1B, o);
            s2B += __shfl_xor_sync(0xffffffffu, s2B, o);
        }
        if (tig == 0) {
            red[gid][w]     = make_float2(s1A, s2A);
            red[gid + 8][w] = make_float2(s1B, s2B);
        }
        __syncthreads();
        if (tid < 16) {
            float s1 = 0.f, s2 = 0.f;
#pragma unroll
            for (int ww = 0; ww < 4; ww++) {
                float2 v = red[tid][ww];
                s1 += v.x; s2 += v.y;
            }
            float mean = s1 * (1.0f / 128.0f);
            float var  = fmaxf(s2 * (1.0f / 128.0f) - mean * mean, 0.0f);
            mi[tid] = make_float2(mean, rsqrtf(var + 1e-5f));
        }
        __syncthreads();

        float2 miA = mi[gid], miB = mi[gid + 8];
        int eA = base + rg * 16 + gid, eB = eA + 8;
#pragma unroll
        for (int jj = 0; jj < 4; jj++) {
            int colb = 32 * w + 8 * jj + 2 * tig;
            if (eA < E) {
                float2 o;
                o.x = (C[jj][0] - miA.x) * miA.y * gg2[jj].x + bt2[jj].x;
                o.y = (C[jj][1] - miA.x) * miA.y * gg2[jj].y + bt2[jj].y;
                *reinterpret_cast<float2*>(hE + (size_t)eA * 128 + colb) = o;
            }
            if (eB < E) {
                float2 o;
                o.x = (C[jj][2] - miB.x) * miB.y * gg2[jj].x + bt2[jj].x;
                o.y = (C[jj][3] - miB.x) * miB.y * gg2[jj].y + bt2[jj].y;
                *reinterpret_cast<float2*>(hE + (size_t)eB * 128 + colb) = o;
            }
        }
        __syncthreads();  // protect red/mi reuse next iteration
    }
}

// ---------------------------------------------------------------------------
extern "C" void kernel_launch(void* const* d_in, const int* in_sizes, int n_in,
                              void* d_out, int out_size)
{
    const float* X    = (const float*)d_in[0];
    const int*   bat  = (const int*)d_in[1];
    const int*   ei   = (const int*)d_in[2];
    const float* Wn   = (const float*)d_in[3];
    const float* bn   = (const float*)d_in[4];
    const float* gn   = (const float*)d_in[5];
    const float* btn  = (const float*)d_in[6];
    const float* We   = (const float*)d_in[7];
    const float* be   = (const float*)d_in[8];
    const float* ge   = (const float*)d_in[9];
    const float* bte  = (const float*)d_in[10];

    int N = in_sizes[0] / 3;
    int E = in_sizes[2] / 2;

    float* hV = (float*)d_out;
    float* hE = hV + (size_t)N * 128;

    k_prep_Bfrag<<<5, 512>>>(We, be);
    k_node_geom<<<(N + 255) / 256, 256>>>(X, bat, N);
    k_node_out<<<(N * 32 + 255) / 256, 256>>>(Wn, bn, gn, btn, hV, N);
    k_edge_fused<<<(E + 127) / 128, 128>>>(X, ei, E, ge, bte, hE);
}

// round 7
// speedup vs baseline: 1.9052x; 1.0361x over previous
#include <cuda_runtime.h>
#include <cuda_bf16.h>
#include <math.h>
#include <stdint.h>

#define NMAX 100000

// Scratch (module-static, no runtime allocation):
__device__ float4 g_q[NMAX * 3];       // per-node frame (3 cols), valid flag in [0].w
__device__ float4 g_nf[NMAX];          // per-node 4 features
__device__ unsigned long long gBfrag[2560]; // precomputed B fragments [s][j][lane]

struct F3 { float x, y, z; };
__device__ __forceinline__ F3 mk3(float a, float b, float c) { F3 r; r.x = a; r.y = b; r.z = c; return r; }
__device__ __forceinline__ F3 sub3(F3 a, F3 b) { return mk3(a.x - b.x, a.y - b.y, a.z - b.z); }
__device__ __forceinline__ float dot3(F3 a, F3 b) { return a.x * b.x + a.y * b.y + a.z * b.z; }
__device__ __forceinline__ F3 cross3(F3 a, F3 b) {
    return mk3(a.y * b.z - a.z * b.y, a.z * b.x - a.x * b.z, a.x * b.y - a.y * b.x);
}
__device__ __forceinline__ F3 nrm3(F3 a) {
    float n = sqrtf(dot3(a, a));
    float s = 1.0f / fmaxf(n, 1e-12f);
    return mk3(a.x * s, a.y * s, a.z * s);
}
__device__ __forceinline__ float signf_(float x) { return (float)((x > 0.0f) - (x < 0.0f)); }

__device__ __forceinline__ uint32_t smem_u32(const void* p) {
    uint32_t a;
    asm("{ .reg .u64 t; cvta.to.shared.u64 t, %1; cvt.u32.u64 %0, t; }" : "=r"(a) : "l"(p));
    return a;
}
__device__ __forceinline__ void mma16816(float* c, uint32_t a0, uint32_t a1, uint32_t a2, uint32_t a3,
                                         uint32_t b0, uint32_t b1) {
    asm volatile(
        "mma.sync.aligned.m16n8k16.row.col.f32.bf16.bf16.f32 "
        "{%0,%1,%2,%3}, {%4,%5,%6,%7}, {%8,%9}, {%0,%1,%2,%3};"
        : "+f"(c[0]), "+f"(c[1]), "+f"(c[2]), "+f"(c[3])
        : "r"(a0), "r"(a1), "r"(a2), "r"(a3), "r"(b0), "r"(b1));
}
__device__ __forceinline__ void ldmatrix_x4(uint32_t& a0, uint32_t& a1, uint32_t& a2, uint32_t& a3, uint32_t addr) {
    asm volatile("ldmatrix.sync.aligned.m8n8.x4.shared.b16 {%0,%1,%2,%3}, [%4];"
                 : "=r"(a0), "=r"(a1), "=r"(a2), "=r"(a3) : "r"(addr));
}
__device__ __forceinline__ float bf16rt(float x) {
    return __bfloat162float(__float2bfloat16(x));
}

// ---------------------------------------------------------------------------
// Kernel 1: per-node geometry
// ---------------------------------------------------------------------------
__global__ void k_node_geom(const float* __restrict__ X, const int* __restrict__ batch, int N)
{
    int i = blockIdx.x * blockDim.x + threadIdx.x;
    if (i >= N) return;

    auto ldx = [&](int j) -> F3 {
        j = j < 0 ? 0 : (j > N - 1 ? N - 1 : j);
        return mk3(X[3 * j], X[3 * j + 1], X[3 * j + 2]);
    };
    F3 xm1 = ldx(i - 1), x0 = ldx(i), xp1 = ldx(i + 1), xp2 = ldx(i + 2);

    int bi   = (i > 0)     && (batch[i] != batch[i - 1]);
    int bip1 = (i + 1 < N) && (batch[i + 1] != batch[i]);
    int bip2 = (i + 2 < N) && (batch[i + 2] != batch[i + 1]);
    bool bad_a = bi || bip1 || (i == 0) || (i == N - 1);
    bool bad_d = bi || bip1 || bip2 || (i == 0) || (i >= N - 2);

    F3 Um = nrm3(sub3(x0,  xm1));
    F3 Uc = nrm3(sub3(xp1, x0));
    F3 Up = nrm3(sub3(xp2, xp1));

    F3 c1 = nrm3(cross3(Um, Uc));
    F3 c2 = nrm3(cross3(Uc, Up));
    float cosd = fminf(fmaxf(dot3(c1, c2), -1.0f + 1e-6f), 1.0f - 1e-6f);
    float sg = signf_(dot3(c2, Um));
    float sdih = sg * sqrtf(fmaxf(1.0f - cosd * cosd, 0.0f));
    float cdih = (sg == 0.0f) ? 1.0f : cosd;

    F3 d0 = nrm3(sub3(xm1, x0));
    F3 d1 = nrm3(sub3(xp1, x0));
    float cosa = dot3(d0, d1);
    float sina = sqrtf(1.0f - cosa * cosa + 1e-6f);

    float4 nf;
    nf.x = bad_d ? 0.0f : sdih;
    nf.y = bad_d ? 0.0f : cdih;
    nf.z = bad_a ? 0.0f : sina;
    nf.w = bad_a ? 0.0f : cosa;
    g_nf[i] = nf;

    F3 bv = nrm3(sub3(Um, Uc));
    F3 nv = nrm3(cross3(Um, Uc));
    F3 cv = cross3(bv, nv);
    float m = bad_a ? 0.0f : 1.0f;
    g_q[i * 3 + 0] = make_float4(bv.x * m, bv.y * m, bv.z * m, m);
    g_q[i * 3 + 1] = make_float4(nv.x * m, nv.y * m, nv.z * m, 0.0f);
    g_q[i * 3 + 2] = make_float4(cv.x * m, cv.y * m, cv.z * m, 0.0f);
}

// ---------------------------------------------------------------------------
// Warp LayerNorm helper (node path)
// ---------------------------------------------------------------------------
__device__ __forceinline__ void ln_store(float4 a, float4 gg, float4 bt, float* __restrict__ dst)
{
    float s1 = a.x + a.y + a.z + a.w;
    float s2 = a.x * a.x + a.y * a.y + a.z * a.z + a.w * a.w;
#pragma unroll
    for (int o = 16; o > 0; o >>= 1) {
        s1 += __shfl_xor_sync(0xffffffffu, s1, o);
        s2 += __shfl_xor_sync(0xffffffffu, s2, o);
    }
    float mean = s1 * (1.0f / 128.0f);
    float var  = fmaxf(s2 * (1.0f / 128.0f) - mean * mean, 0.0f);
    float inv  = rsqrtf(var + 1e-5f);
    float4 o4;
    o4.x = (a.x - mean) * inv * gg.x + bt.x;
    o4.y = (a.y - mean) * inv * gg.y + bt.y;
    o4.z = (a.z - mean) * inv * gg.z + bt.z;
    o4.w = (a.w - mean) * inv * gg.w + bt.w;
    *reinterpret_cast<float4*>(dst) = o4;
}

// ---------------------------------------------------------------------------
// Kernel 2: h_V, 1 warp per node
// ---------------------------------------------------------------------------
__global__ void k_node_out(const float* __restrict__ Wn, const float* __restrict__ bn,
                           const float* __restrict__ gn, const float* __restrict__ bet,
                           float* __restrict__ hV, int N)
{
    int gw   = (blockIdx.x * blockDim.x + threadIdx.x) >> 5;
    int lane = threadIdx.x & 31;
    if (gw >= N) return;
    int c = 4 * lane;
    float4 w0 = *reinterpret_cast<const float4*>(Wn + 0 * 128 + c);
    float4 w1 = *reinterpret_cast<const float4*>(Wn + 1 * 128 + c);
    float4 w2 = *reinterpret_cast<const float4*>(Wn + 2 * 128 + c);
    float4 w3 = *reinterpret_cast<const float4*>(Wn + 3 * 128 + c);
    float4 bb = *reinterpret_cast<const float4*>(bn + c);
    float4 gg = *reinterpret_cast<const float4*>(gn + c);
    float4 bt = *reinterpret_cast<const float4*>(bet + c);

    float4 f = g_nf[gw];
    float4 a;
    a.x = bb.x + f.x * w0.x + f.y * w1.x + f.z * w2.x + f.w * w3.x;
    a.y = bb.y + f.x * w0.y + f.y * w1.y + f.z * w2.y + f.w * w3.y;
    a.z = bb.z + f.x * w0.z + f.y * w1.z + f.z * w2.z + f.w * w3.z;
    a.w = bb.w + f.x * w0.w + f.y * w1.w + f.z * w2.w + f.w * w3.w;
    ln_store(a, gg, bt, hV + (size_t)gw * 128 + c);
}

// ---------------------------------------------------------------------------
// Kernel 3-prep: B fragments for mma.m16n8k16 (run once, tiny).
// W' (K'=80 x 128): rows 0..22=hi(W), 23..45=lo(W), 46..68=hi(W),
// 69=hi(bias), 70=lo(bias), 71..79=0.
// A' cols: 0..22=hi(f), 23..45=hi(f), 46..68=lo(f), 69..70=1  =>
// A'B' = hi.Whi + hi.Wlo + lo.Whi + bias   (drops lo.lo ~ 2^-18)
// ---------------------------------------------------------------------------
__global__ void k_prep_Bfrag(const float* __restrict__ We, const float* __restrict__ be)
{
    int idx = blockIdx.x * blockDim.x + threadIdx.x;
    if (idx >= 2560) return;
    int lane = idx & 31, j = (idx >> 5) & 15, s = idx >> 9;
    int gid = lane >> 2, tig = lane & 3, n = 8 * j + gid;

    auto wv = [&](int r) -> float {
        if (r < 23)  return bf16rt(We[r * 128 + n]);
        if (r < 46)  { float x = We[(r - 23) * 128 + n]; return x - bf16rt(x); }
        if (r < 69)  return bf16rt(We[(r - 46) * 128 + n]);
        if (r == 69) return bf16rt(be[n]);
        if (r == 70) { float x = be[n]; return x - bf16rt(x); }
        return 0.0f;
    };
    int k0 = 16 * s + 2 * tig;
    __nv_bfloat162 p0 = __floats2bfloat162_rn(wv(k0),     wv(k0 + 1));
    __nv_bfloat162 p1 = __floats2bfloat162_rn(wv(k0 + 8), wv(k0 + 9));
    uint32_t b0 = *reinterpret_cast<uint32_t*>(&p0);
    uint32_t b1 = *reinterpret_cast<uint32_t*>(&p1);
    gBfrag[idx] = ((unsigned long long)b1 << 32) | b0;
}

// ---------------------------------------------------------------------------
// Kernel 3: FUSED edge features + tensor-core GEMM + LN.
// Block = 128 threads = 4 warps; tile = 128 edges.
// ---------------------------------------------------------------------------
__global__ void __launch_bounds__(128, 5)
k_edge_fused(const float* __restrict__ X, const int* __restrict__ ei, int E,
             const float* __restrict__ ge, const float* __restrict__ bet,
             float* __restrict__ hE)
{
    __shared__ __nv_bfloat16 A_img[128 * 88];
    __shared__ float2 red[2][16][5];   // double-buffered, padded stride

    int tid = threadIdx.x, w = tid >> 5, lane = tid & 31;
    int gid = lane >> 2, tig = lane & 3;
    int base = blockIdx.x * 128;

    // ---- Phase 1: per-thread edge features -> A image (STS.128, no conflicts)
    {
        int e = base + tid;
        float f[23];
#pragma unroll
        for (int k = 0; k < 23; k++) f[k] = 0.0f;
        if (e < E) {
            int s = __ldg(ei + e);
            int t = __ldg(ei + E + e);

            float4 tb = g_q[t * 3 + 0], tn = g_q[t * 3 + 1], tc = g_q[t * 3 + 2];
            float4 sb = g_q[s * 3 + 0], sn = g_q[s * 3 + 1], sc = g_q[s * 3 + 2];

            float dvx = __ldg(X + 3 * s)     - __ldg(X + 3 * t);
            float dvy = __ldg(X + 3 * s + 1) - __ldg(X + 3 * t + 1);
            float dvz = __ldg(X + 3 * s + 2) - __ldg(X + 3 * t + 2);
            float d2   = dvx * dvx + dvy * dvy + dvz * dvz;
            float dist = sqrtf(d2 + 1e-6f);
            float rinv = 1.0f / fmaxf(sqrtf(d2), 1e-12f);
            float dhx = dvx * rinv, dhy = dvy * rinv, dhz = dvz * rinv;

            float Rxx = tb.x * sb.x + tb.y * sb.y + tb.z * sb.z;
            float Rxy = tb.x * sn.x + tb.y * sn.y + tb.z * sn.z;
            float Rxz = tb.x * sc.x + tb.y * sc.y + tb.z * sc.z;
            float Ryx = tn.x * sb.x + tn.y * sb.y + tn.z * sb.z;
            float Ryy = tn.x * sn.x + tn.y * sn.y + tn.z * sn.z;
            float Ryz = tn.x * sc.x + tn.y * sc.y + tn.z * sc.z;
            float Rzx = tc.x * sb.x + tc.y * sb.y + tc.z * sb.z;
            float Rzy = tc.x * sn.x + tc.y * sn.y + tc.z * sn.z;
            float Rzz = tc.x * sc.x + tc.y * sc.y + tc.z * sc.z;

            float m0 = 0.5f * sqrtf(fabsf(1.0f + Rxx - Ryy - Rzz));
            float m1 = 0.5f * sqrtf(fabsf(1.0f - Rxx + Ryy - Rzz));
            float m2 = 0.5f * sqrtf(fabsf(1.0f - Rxx - Ryy + Rzz));
            float q0 = signf_(Rzy - Ryz) * m0;
            float q1 = signf_(Rxz - Rzx) * m1;
            float q2 = signf_(Ryx - Rxy) * m2;
            float qw = 0.5f * sqrtf(fmaxf(1.0f + Rxx + Ryy + Rzz, 0.0f));
            float qn = sqrtf(q0 * q0 + q1 * q1 + q2 * q2 + qw * qw);
            float vm = (tb.w * sb.w) / fmaxf(qn, 1e-12f);

            f[0] = q0 * vm; f[1] = q1 * vm; f[2] = q2 * vm; f[3] = qw * vm;
#pragma unroll
            for (int k = 0; k < 16; k++) {
                float mu = (float)k * (20.0f / 15.0f);
                float tt = (dist - mu) * 0.8f;
                f[4 + k] = __expf(-tt * tt);
            }
            f[20] = tb.x * dhx + tb.y * dhy + tb.z * dhz;
            f[21] = tn.x * dhx + tn.y * dhy + tn.z * dhz;
            f[22] = tc.x * dhx + tc.y * dhy + tc.z * dhz;
        }

        // col c: 0..22 hi(f[c]); 23..45 hi(f[c-23]); 46..68 lo(f[c-46]); 69,70=1; else 0
        uint4* Av = reinterpret_cast<uint4*>(A_img + tid * 88);
#pragma unroll
        for (int g = 0; g < 11; g++) {
            uint32_t au[4];
#pragma unroll
            for (int h = 0; h < 4; h++) {
                int c0 = 8 * g + 2 * h, c1 = c0 + 1;
                float a0 = (c0 < 23) ? bf16rt(f[c0])
                         : (c0 < 46) ? bf16rt(f[c0 - 23])
                         : (c0 < 69) ? (f[c0 - 46] - bf16rt(f[c0 - 46]))
                         : (c0 < 71) ? 1.0f : 0.0f;
                float a1 = (c1 < 23) ? bf16rt(f[c1])
                         : (c1 < 46) ? bf16rt(f[c1 - 23])
                         : (c1 < 69) ? (f[c1 - 46] - bf16rt(f[c1 - 46]))
                         : (c1 < 71) ? 1.0f : 0.0f;
                __nv_bfloat162 p = __floats2bfloat162_rn(a0, a1);
                au[h] = *reinterpret_cast<uint32_t*>(&p);
            }
            Av[g] = make_uint4(au[0], au[1], au[2], au[3]);
        }
    }
    __syncthreads();

    // ---- B fragments + LN params (loaded after phase 1 to cut reg peak) ----
    uint32_t B0[5][4], B1[5][4];
#pragma unroll
    for (int s = 0; s < 5; s++)
#pragma unroll
        for (int jj = 0; jj < 4; jj++) {
            unsigned long long v = gBfrag[(s * 16 + (w * 4 + jj)) * 32 + lane];
            B0[s][jj] = (uint32_t)v;
            B1[s][jj] = (uint32_t)(v >> 32);
        }
    float2 gg2[4], bt2[4];
#pragma unroll
    for (int jj = 0; jj < 4; jj++) {
        int colb = 32 * w + 8 * jj + 2 * tig;
        gg2[jj] = *reinterpret_cast<const float2*>(ge + colb);
        bt2[jj] = *reinterpret_cast<const float2*>(bet + colb);
    }

    uint32_t aBase = smem_u32(A_img)
                   + ((lane & 7) + ((lane & 8) ? 8 : 0)) * 176
                   + ((lane & 16) ? 16 : 0);

    // ---- Phase 2: 8 row-groups of 16 edges, ONE sync per rg ----
#pragma unroll 1
    for (int rg = 0; rg < 8; rg++) {
        int buf = rg & 1;
        float C[4][4];
#pragma unroll
        for (int jj = 0; jj < 4; jj++)
#pragma unroll
            for (int q = 0; q < 4; q++) C[jj][q] = 0.0f;

        uint32_t aAddr = aBase + rg * (16 * 176);
#pragma unroll
        for (int s = 0; s < 5; s++) {
            uint32_t a0, a1, a2, a3;
            ldmatrix_x4(a0, a1, a2, a3, aAddr + s * 32);
#pragma unroll
            for (int jj = 0; jj < 4; jj++)
                mma16816(C[jj], a0, a1, a2, a3, B0[s][jj], B1[s][jj]);
        }

        // per-warp LN partials for rows gid / gid+8
        float s1A = 0.f, s2A = 0.f, s1B = 0.f, s2B = 0.f;
#pragma unroll
        for (int jj = 0; jj < 4; jj++) {
            s1A += C[jj][0] + C[jj][1];
            s2A += C[jj][0] * C[jj][0] + C[jj][1] * C[jj][1];
            s1B += C[jj][2] + C[jj][3];
            s2B += C[jj][2] * C[jj][2] + C[jj][3] * C[jj][3];
        }
#pragma unroll
        for (int o = 1; o <= 2; o <<= 1) {
            s1A += __shfl_xor_sync(0xffffffffu, s1A, o);
            s2A += __shfl_xor_sync(0xffffffffu, s2A, o);
            s1B += __shfl_xor_sync(0xffffffffu, s1B, o);
            s2B += __shfl_xor_sync(0xffffffffu, s2B, o);
        }
        if (tig == 0) {
            red[buf][gid][w]     = make_float2(s1A, s2A);
            red[buf][gid + 8][w] = make_float2(s1B, s2B);
        }
        __syncthreads();

        // every thread finalizes its rows' stats (broadcast LDS, no 2nd sync)
        float u1 = 0.f, u2 = 0.f, v1 = 0.f, v2 = 0.f;
#pragma unroll
        for (int ww = 0; ww < 4; ww++) {
            float2 a = red[buf][gid][ww];
            float2 b = red[buf][gid + 8][ww];
            u1 += a.x; u2 += a.y;
            v1 += b.x; v2 += b.y;
        }
        float meanA = u1 * (1.0f / 128.0f);
        float invA  = rsqrtf(fmaxf(u2 * (1.0f / 128.0f) - meanA * meanA, 0.0f) + 1e-5f);
        float meanB = v1 * (1.0f / 128.0f);
        float invB  = rsqrtf(fmaxf(v2 * (1.0f / 128.0f) - meanB * meanB, 0.0f) + 1e-5f);

        int eA = base + rg * 16 + gid, eB = eA + 8;
#pragma unroll
        for (int jj = 0; jj < 4; jj++) {
            int colb = 32 * w + 8 * jj + 2 * tig;
            if (eA < E) {
                float2 o;
                o.x = (C[jj][0] - meanA) * invA * gg2[jj].x + bt2[jj].x;
                o.y = (C[jj][1] - meanA) * invA * gg2[jj].y + bt2[jj].y;
                *reinterpret_cast<float2*>(hE + (size_t)eA * 128 + colb) = o;
            }
            if (eB < E) {
                float2 o;
                o.x = (C[jj][2] - meanB) * invB * gg2[jj].x + bt2[jj].x;
                o.y = (C[jj][3] - meanB) * invB * gg2[jj].y + bt2[jj].y;
                *reinterpret_cast<float2*>(hE + (size_t)eB * 128 + colb) = o;
            }
        }
    }
}

// ---------------------------------------------------------------------------
extern "C" void kernel_launch(void* const* d_in, const int* in_sizes, int n_in,
                              void* d_out, int out_size)
{
    const float* X    = (const float*)d_in[0];
    const int*   bat  = (const int*)d_in[1];
    const int*   ei   = (const int*)d_in[2];
    const float* Wn   = (const float*)d_in[3];
    const float* bn   = (const float*)d_in[4];
    const float* gn   = (const float*)d_in[5];
    const float* btn  = (const float*)d_in[6];
    const float* We   = (const float*)d_in[7];
    const float* be   = (const float*)d_in[8];
    const float* ge   = (const float*)d_in[9];
    const float* bte  = (const float*)d_in[10];

    int N = in_sizes[0] / 3;
    int E = in_sizes[2] / 2;

    float* hV = (float*)d_out;
    float* hE = hV + (size_t)N * 128;

    k_prep_Bfrag<<<5, 512>>>(We, be);
    k_node_geom<<<(N + 255) / 256, 256>>>(X, bat, N);
    k_node_out<<<(N * 32 + 255) / 256, 256>>>(Wn, bn, gn, btn, hV, N);
    k_edge_fused<<<(E + 127) / 128, 128>>>(X, ei, E, ge, bte, hE);
}

// round 8
// speedup vs baseline: 2.2393x; 1.1754x over previous
#include <cuda_runtime.h>
#include <cuda_bf16.h>
#include <math.h>
#include <stdint.h>

#define NMAX 100000

// Scratch (module-static):
__device__ float4 g_qn[NMAX * 2];      // per-node: [0]=(qx,qy,qz,qw) frame quaternion, [1]=(X.x,X.y,X.z,valid)
__device__ float4 g_nf[NMAX];          // per-node 4 features
__device__ unsigned long long gBfrag[2560]; // precomputed B fragments [s][j][lane]

struct F3 { float x, y, z; };
__device__ __forceinline__ F3 mk3(float a, float b, float c) { F3 r; r.x = a; r.y = b; r.z = c; return r; }
__device__ __forceinline__ F3 sub3(F3 a, F3 b) { return mk3(a.x - b.x, a.y - b.y, a.z - b.z); }
__device__ __forceinline__ float dot3(F3 a, F3 b) { return a.x * b.x + a.y * b.y + a.z * b.z; }
__device__ __forceinline__ F3 cross3(F3 a, F3 b) {
    return mk3(a.y * b.z - a.z * b.y, a.z * b.x - a.x * b.z, a.x * b.y - a.y * b.x);
}
__device__ __forceinline__ F3 nrm3(F3 a) {
    float n = sqrtf(dot3(a, a));
    float s = 1.0f / fmaxf(n, 1e-12f);
    return mk3(a.x * s, a.y * s, a.z * s);
}
__device__ __forceinline__ float signf_(float x) { return (float)((x > 0.0f) - (x < 0.0f)); }

__device__ __forceinline__ uint32_t smem_u32(const void* p) {
    uint32_t a;
    asm("{ .reg .u64 t; cvta.to.shared.u64 t, %1; cvt.u32.u64 %0, t; }" : "=r"(a) : "l"(p));
    return a;
}
__device__ __forceinline__ void mma16816(float* c, uint32_t a0, uint32_t a1, uint32_t a2, uint32_t a3,
                                         uint32_t b0, uint32_t b1) {
    asm volatile(
        "mma.sync.aligned.m16n8k16.row.col.f32.bf16.bf16.f32 "
        "{%0,%1,%2,%3}, {%4,%5,%6,%7}, {%8,%9}, {%0,%1,%2,%3};"
        : "+f"(c[0]), "+f"(c[1]), "+f"(c[2]), "+f"(c[3])
        : "r"(a0), "r"(a1), "r"(a2), "r"(a3), "r"(b0), "r"(b1));
}
__device__ __forceinline__ void ldmatrix_x4(uint32_t& a0, uint32_t& a1, uint32_t& a2, uint32_t& a3, uint32_t addr) {
    asm volatile("ldmatrix.sync.aligned.m8n8.x4.shared.b16 {%0,%1,%2,%3}, [%4];"
                 : "=r"(a0), "=r"(a1), "=r"(a2), "=r"(a3) : "r"(addr));
}
__device__ __forceinline__ float bf16rt(float x) {
    return __bfloat162float(__float2bfloat16(x));
}

// ---------------------------------------------------------------------------
// Kernel 1: per-node geometry -> node feats + frame quaternion record
// ---------------------------------------------------------------------------
__global__ void k_node_geom(const float* __restrict__ X, const int* __restrict__ batch, int N)
{
    int i = blockIdx.x * blockDim.x + threadIdx.x;
    if (i >= N) return;

    auto ldx = [&](int j) -> F3 {
        j = j < 0 ? 0 : (j > N - 1 ? N - 1 : j);
        return mk3(X[3 * j], X[3 * j + 1], X[3 * j + 2]);
    };
    F3 xm1 = ldx(i - 1), x0 = ldx(i), xp1 = ldx(i + 1), xp2 = ldx(i + 2);

    int bi   = (i > 0)     && (batch[i] != batch[i - 1]);
    int bip1 = (i + 1 < N) && (batch[i + 1] != batch[i]);
    int bip2 = (i + 2 < N) && (batch[i + 2] != batch[i + 1]);
    bool bad_a = bi || bip1 || (i == 0) || (i == N - 1);
    bool bad_d = bi || bip1 || bip2 || (i == 0) || (i >= N - 2);

    F3 Um = nrm3(sub3(x0,  xm1));
    F3 Uc = nrm3(sub3(xp1, x0));
    F3 Up = nrm3(sub3(xp2, xp1));

    F3 c1 = nrm3(cross3(Um, Uc));
    F3 c2 = nrm3(cross3(Uc, Up));
    float cosd = fminf(fmaxf(dot3(c1, c2), -1.0f + 1e-6f), 1.0f - 1e-6f);
    float sg = signf_(dot3(c2, Um));
    float sdih = sg * sqrtf(fmaxf(1.0f - cosd * cosd, 0.0f));
    float cdih = (sg == 0.0f) ? 1.0f : cosd;

    F3 d0 = nrm3(sub3(xm1, x0));
    F3 d1 = nrm3(sub3(xp1, x0));
    float cosa = dot3(d0, d1);
    float sina = sqrtf(1.0f - cosa * cosa + 1e-6f);

    float4 nf;
    nf.x = bad_d ? 0.0f : sdih;
    nf.y = bad_d ? 0.0f : cdih;
    nf.z = bad_a ? 0.0f : sina;
    nf.w = bad_a ? 0.0f : cosa;
    g_nf[i] = nf;

    // Local frame Q = [bv nv cv] (columns); convert to quaternion (Shepperd).
    F3 bv = nrm3(sub3(Um, Uc));
    F3 nv = nrm3(cross3(Um, Uc));
    F3 cv = cross3(bv, nv);

    float qx = 0.0f, qy = 0.0f, qz = 0.0f, qw = 1.0f;
    if (!bad_a) {
        // matrix entries: column0=bv, column1=nv, column2=cv
        float m00 = bv.x, m10 = bv.y, m20 = bv.z;
        float m01 = nv.x, m11 = nv.y, m21 = nv.z;
        float m02 = cv.x, m12 = cv.y, m22 = cv.z;
        float tr = m00 + m11 + m22;
        if (tr > 0.0f) {
            float S = sqrtf(fmaxf(tr + 1.0f, 0.0f)) * 2.0f;
            S = fmaxf(S, 1e-20f);
            qw = 0.25f * S;
            qx = (m21 - m12) / S;
            qy = (m02 - m20) / S;
            qz = (m10 - m01) / S;
        } else if (m00 >= m11 && m00 >= m22) {
            float S = sqrtf(fmaxf(1.0f + m00 - m11 - m22, 0.0f)) * 2.0f;
            S = fmaxf(S, 1e-20f);
            qw = (m21 - m12) / S;
            qx = 0.25f * S;
            qy = (m01 + m10) / S;
            qz = (m02 + m20) / S;
        } else if (m11 >= m22) {
            float S = sqrtf(fmaxf(1.0f + m11 - m00 - m22, 0.0f)) * 2.0f;
            S = fmaxf(S, 1e-20f);
            qw = (m02 - m20) / S;
            qx = (m01 + m10) / S;
            qy = 0.25f * S;
            qz = (m12 + m21) / S;
        } else {
            float S = sqrtf(fmaxf(1.0f + m22 - m00 - m11, 0.0f)) * 2.0f;
            S = fmaxf(S, 1e-20f);
            qw = (m10 - m01) / S;
            qx = (m02 + m20) / S;
            qy = (m12 + m21) / S;
            qz = 0.25f * S;
        }
        // normalize (guard degenerate frames)
        float nq = rsqrtf(fmaxf(qx * qx + qy * qy + qz * qz + qw * qw, 1e-24f));
        qx *= nq; qy *= nq; qz *= nq; qw *= nq;
    }
    g_qn[i * 2 + 0] = make_float4(qx, qy, qz, qw);
    g_qn[i * 2 + 1] = make_float4(x0.x, x0.y, x0.z, bad_a ? 0.0f : 1.0f);
}

// ---------------------------------------------------------------------------
// Warp LayerNorm helper (node path)
// ---------------------------------------------------------------------------
__device__ __forceinline__ void ln_store(float4 a, float4 gg, float4 bt, float* __restrict__ dst)
{
    float s1 = a.x + a.y + a.z + a.w;
    float s2 = a.x * a.x + a.y * a.y + a.z * a.z + a.w * a.w;
#pragma unroll
    for (int o = 16; o > 0; o >>= 1) {
        s1 += __shfl_xor_sync(0xffffffffu, s1, o);
        s2 += __shfl_xor_sync(0xffffffffu, s2, o);
    }
    float mean = s1 * (1.0f / 128.0f);
    float var  = fmaxf(s2 * (1.0f / 128.0f) - mean * mean, 0.0f);
    float inv  = rsqrtf(var + 1e-5f);
    float4 o4;
    o4.x = (a.x - mean) * inv * gg.x + bt.x;
    o4.y = (a.y - mean) * inv * gg.y + bt.y;
    o4.z = (a.z - mean) * inv * gg.z + bt.z;
    o4.w = (a.w - mean) * inv * gg.w + bt.w;
    *reinterpret_cast<float4*>(dst) = o4;
}

// ---------------------------------------------------------------------------
// Kernel 2: h_V, 1 warp per node
// ---------------------------------------------------------------------------
__global__ void k_node_out(const float* __restrict__ Wn, const float* __restrict__ bn,
                           const float* __restrict__ gn, const float* __restrict__ bet,
                           float* __restrict__ hV, int N)
{
    int gw   = (blockIdx.x * blockDim.x + threadIdx.x) >> 5;
    int lane = threadIdx.x & 31;
    if (gw >= N) return;
    int c = 4 * lane;
    float4 w0 = *reinterpret_cast<const float4*>(Wn + 0 * 128 + c);
    float4 w1 = *reinterpret_cast<const float4*>(Wn + 1 * 128 + c);
    float4 w2 = *reinterpret_cast<const float4*>(Wn + 2 * 128 + c);
    float4 w3 = *reinterpret_cast<const float4*>(Wn + 3 * 128 + c);
    float4 bb = *reinterpret_cast<const float4*>(bn + c);
    float4 gg = *reinterpret_cast<const float4*>(gn + c);
    float4 bt = *reinterpret_cast<const float4*>(bet + c);

    float4 f = g_nf[gw];
    float4 a;
    a.x = bb.x + f.x * w0.x + f.y * w1.x + f.z * w2.x + f.w * w3.x;
    a.y = bb.y + f.x * w0.y + f.y * w1.y + f.z * w2.y + f.w * w3.y;
    a.z = bb.z + f.x * w0.z + f.y * w1.z + f.z * w2.z + f.w * w3.z;
    a.w = bb.w + f.x * w0.w + f.y * w1.w + f.z * w2.w + f.w * w3.w;
    ln_store(a, gg, bt, hV + (size_t)gw * 128 + c);
}

// ---------------------------------------------------------------------------
// Kernel 3-prep: B fragments for mma.m16n8k16 (run once, tiny).
// K' = 80 rows: 0..22=hi(W), 23..45=lo(W), 46..68=hi(W), 69=hi(b), 70=lo(b), rest 0.
// COLUMN PERMUTATION: within each warp's 32-col slice, logical tile col
// (jj, n) with n=2t+e maps to physical weight column 32w + 8t + 2jj + e,
// so each lane's C registers end up owning 8 contiguous output columns.
// ---------------------------------------------------------------------------
__global__ void k_prep_Bfrag(const float* __restrict__ We, const float* __restrict__ be)
{
    int idx = blockIdx.x * blockDim.x + threadIdx.x;
    if (idx >= 2560) return;
    int lane = idx & 31, j = (idx >> 5) & 15, s = idx >> 9;
    int gid = lane >> 2, tig = lane & 3;
    int w = j >> 2, jj = j & 3;
    // physical weight column for B-fragment col index gid of tile (w,jj):
    int n = 32 * w + 8 * (gid >> 1) + 2 * jj + (gid & 1);

    auto wv = [&](int r) -> float {
        if (r < 23)  return bf16rt(We[r * 128 + n]);
        if (r < 46)  { float x = We[(r - 23) * 128 + n]; return x - bf16rt(x); }
        if (r < 69)  return bf16rt(We[(r - 46) * 128 + n]);
        if (r == 69) return bf16rt(be[n]);
        if (r == 70) { float x = be[n]; return x - bf16rt(x); }
        return 0.0f;
    };
    int k0 = 16 * s + 2 * tig;
    __nv_bfloat162 p0 = __floats2bfloat162_rn(wv(k0),     wv(k0 + 1));
    __nv_bfloat162 p1 = __floats2bfloat162_rn(wv(k0 + 8), wv(k0 + 9));
    uint32_t b0 = *reinterpret_cast<uint32_t*>(&p0);
    uint32_t b1 = *reinterpret_cast<uint32_t*>(&p1);
    gBfrag[idx] = ((unsigned long long)b1 << 32) | b0;
}

// ---------------------------------------------------------------------------
// Kernel 3: FUSED edge features (quaternion path) + tensor GEMM + LN.
// Block = 128 threads = 4 warps; tile = 128 edges.
// ---------------------------------------------------------------------------
__global__ void __launch_bounds__(128, 5)
k_edge_fused(const int* __restrict__ ei, int E,
             const float* __restrict__ ge, const float* __restrict__ bet,
             float* __restrict__ hE)
{
    __shared__ __nv_bfloat16 A_img[128 * 88];
    __shared__ float2 red[2][16][5];   // double-buffered, padded stride

    int tid = threadIdx.x, w = tid >> 5, lane = tid & 31;
    int gid = lane >> 2, tig = lane & 3;
    int base = blockIdx.x * 128;

    // ---- Phase 1: per-thread edge features via quaternion composition ----
    {
        int e = base + tid;
        float f[23];
#pragma unroll
        for (int k = 0; k < 23; k++) f[k] = 0.0f;
        if (e < E) {
            int s = __ldg(ei + e);
            int t = __ldg(ei + E + e);

            float4 qt = g_qn[2 * t],     xt = g_qn[2 * t + 1];
            float4 qs = g_qn[2 * s],     xs = g_qn[2 * s + 1];

            float dvx = xs.x - xt.x, dvy = xs.y - xt.y, dvz = xs.z - xt.z;
            float d2   = dvx * dvx + dvy * dvy + dvz * dvz;
            float dist = sqrtf(d2 + 1e-6f);
            float rinv = 1.0f / fmaxf(sqrtf(d2), 1e-12f);
            float dhx = dvx * rinv, dhy = dvy * rinv, dhz = dvz * rinv;

            // q_rel = conj(q_t) * q_s
            float rw = qt.w * qs.w + qt.x * qs.x + qt.y * qs.y + qt.z * qs.z;
            float rx = qt.w * qs.x - qs.w * qt.x - (qt.y * qs.z - qt.z * qs.y);
            float ry = qt.w * qs.y - qs.w * qt.y - (qt.z * qs.x - qt.x * qs.z);
            float rz = qt.w * qs.z - qs.w * qt.z - (qt.x * qs.y - qt.y * qs.x);

            float sgnw = signf_(rw);
            float qn2 = rx * rx + ry * ry + rz * rz + rw * rw;
            float vm = (xt.w * xs.w) * sgnw / fmaxf(sqrtf(qn2), 1e-12f);
            f[0] = rx * vm; f[1] = ry * vm; f[2] = rz * vm; f[3] = rw * vm;

#pragma unroll
            for (int k = 0; k < 16; k++) {
                float mu = (float)k * (20.0f / 15.0f);
                float tt = (dist - mu) * 0.8f;
                f[4 + k] = __expf(-tt * tt);
            }

            // direct = Q_t^T dhat = rotate dhat by conj(q_t); mask by valid_t
            {
                float ax = qt.x, ay = qt.y, az = qt.z, aw = qt.w;
                float t1x = ay * dhz - az * dhy;
                float t1y = az * dhx - ax * dhz;
                float t1z = ax * dhy - ay * dhx;
                float ux = ay * t1z - az * t1y;
                float uy = az * t1x - ax * t1z;
                float uz = ax * t1y - ay * t1x;
                f[20] = (dhx - 2.0f * aw * t1x + 2.0f * ux) * xt.w;
                f[21] = (dhy - 2.0f * aw * t1y + 2.0f * uy) * xt.w;
                f[22] = (dhz - 2.0f * aw * t1z + 2.0f * uz) * xt.w;
            }
        }

        // col c: 0..22 hi(f[c]); 23..45 hi(f[c-23]); 46..68 lo(f[c-46]); 69,70=1; else 0
        uint4* Av = reinterpret_cast<uint4*>(A_img + tid * 88);
#pragma unroll
        for (int g = 0; g < 11; g++) {
            uint32_t au[4];
#pragma unroll
            for (int h = 0; h < 4; h++) {
                int c0 = 8 * g + 2 * h, c1 = c0 + 1;
                float a0 = (c0 < 23) ? bf16rt(f[c0])
                         : (c0 < 46) ? bf16rt(f[c0 - 23])
                         : (c0 < 69) ? (f[c0 - 46] - bf16rt(f[c0 - 46]))
                         : (c0 < 71) ? 1.0f : 0.0f;
                float a1 = (c1 < 23) ? bf16rt(f[c1])
                         : (c1 < 46) ? bf16rt(f[c1 - 23])
                         : (c1 < 69) ? (f[c1 - 46] - bf16rt(f[c1 - 46]))
                         : (c1 < 71) ? 1.0f : 0.0f;
                __nv_bfloat162 p = __floats2bfloat162_rn(a0, a1);
                au[h] = *reinterpret_cast<uint32_t*>(&p);
            }
            Av[g] = make_uint4(au[0], au[1], au[2], au[3]);
        }
    }
    __syncthreads();

    // ---- B fragments + LN params ----
    uint32_t B0[5][4], B1[5][4];
#pragma unroll
    for (int s = 0; s < 5; s++)
#pragma unroll
        for (int jj = 0; jj < 4; jj++) {
            unsigned long long v = gBfrag[(s * 16 + (w * 4 + jj)) * 32 + lane];
            B0[s][jj] = (uint32_t)v;
            B1[s][jj] = (uint32_t)(v >> 32);
        }
    // with the column permutation, lane's C[jj][0/1] = cols 32w + 8tig + 2jj + {0,1}
    float2 gg2[4], bt2[4];
#pragma unroll
    for (int jj = 0; jj < 4; jj++) {
        int colb = 32 * w + 8 * tig + 2 * jj;
        gg2[jj] = *reinterpret_cast<const float2*>(ge + colb);
        bt2[jj] = *reinterpret_cast<const float2*>(bet + colb);
    }

    uint32_t aBase = smem_u32(A_img)
                   + ((lane & 7) + ((lane & 8) ? 8 : 0)) * 176
                   + ((lane & 16) ? 16 : 0);

    // ---- Phase 2: 8 row-groups of 16 edges, one sync each ----
#pragma unroll 1
    for (int rg = 0; rg < 8; rg++) {
        int buf = rg & 1;
        float C[4][4];
#pragma unroll
        for (int jj = 0; jj < 4; jj++)
#pragma unroll
            for (int q = 0; q < 4; q++) C[jj][q] = 0.0f;

        uint32_t aAddr = aBase + rg * (16 * 176);
#pragma unroll
        for (int s = 0; s < 5; s++) {
            uint32_t a0, a1, a2, a3;
            ldmatrix_x4(a0, a1, a2, a3, aAddr + s * 32);
#pragma unroll
            for (int jj = 0; jj < 4; jj++)
                mma16816(C[jj], a0, a1, a2, a3, B0[s][jj], B1[s][jj]);
        }

        float s1A = 0.f, s2A = 0.f, s1B = 0.f, s2B = 0.f;
#pragma unroll
        for (int jj = 0; jj < 4; jj++) {
            s1A += C[jj][0] + C[jj][1];
            s2A += C[jj][0] * C[jj][0] + C[jj][1] * C[jj][1];
            s1B += C[jj][2] + C[jj][3];
            s2B += C[jj][2] * C[jj][2] + C[jj][3] * C[jj][3];
        }
#pragma unroll
        for (int o = 1; o <= 2; o <<= 1) {
            s1A += __shfl_xor_sync(0xffffffffu, s1A, o);
            s2A += __shfl_xor_sync(0xffffffffu, s2A, o);
            s1B += __shfl_xor_sync(0xffffffffu, s1B, o);
            s2B += __shfl_xor_sync(0xffffffffu, s2B, o);
        }
        if (tig == 0) {
            red[buf][gid][w]     = make_float2(s1A, s2A);
            red[buf][gid + 8][w] = make_float2(s1B, s2B);
        }
        __syncthreads();

        float u1 = 0.f, u2 = 0.f, v1 = 0.f, v2 = 0.f;
#pragma unroll
        for (int ww = 0; ww < 4; ww++) {
            float2 a = red[buf][gid][ww];
            float2 b = red[buf][gid + 8][ww];
            u1 += a.x; u2 += a.y;
            v1 += b.x; v2 += b.y;
        }
        float meanA = u1 * (1.0f / 128.0f);
        float invA  = rsqrtf(fmaxf(u2 * (1.0f / 128.0f) - meanA * meanA, 0.0f) + 1e-5f);
        float meanB = v1 * (1.0f / 128.0f);
        float invB  = rsqrtf(fmaxf(v2 * (1.0f / 128.0f) - meanB * meanB, 0.0f) + 1e-5f);

        int eA = base + rg * 16 + gid, eB = eA + 8;
        int colb = 32 * w + 8 * tig;   // this lane's 8 contiguous columns
        if (eA < E) {
            float4 lo, hi;
            lo.x = (C[0][0] - meanA) * invA * gg2[0].x + bt2[0].x;
            lo.y = (C[0][1] - meanA) * invA * gg2[0].y + bt2[0].y;
            lo.z = (C[1][0] - meanA) * invA * gg2[1].x + bt2[1].x;
            lo.w = (C[1][1] - meanA) * invA * gg2[1].y + bt2[1].y;
            hi.x = (C[2][0] - meanA) * invA * gg2[2].x + bt2[2].x;
            hi.y = (C[2][1] - meanA) * invA * gg2[2].y + bt2[2].y;
            hi.z = (C[3][0] - meanA) * invA * gg2[3].x + bt2[3].x;
            hi.w = (C[3][1] - meanA) * invA * gg2[3].y + bt2[3].y;
            float* dst = hE + (size_t)eA * 128 + colb;
            *reinterpret_cast<float4*>(dst)     = lo;
            *reinterpret_cast<float4*>(dst + 4) = hi;
        }
        if (eB < E) {
            float4 lo, hi;
            lo.x = (C[0][2] - meanB) * invB * gg2[0].x + bt2[0].x;
            lo.y = (C[0][3] - meanB) * invB * gg2[0].y + bt2[0].y;
            lo.z = (C[1][2] - meanB) * invB * gg2[1].x + bt2[1].x;
            lo.w = (C[1][3] - meanB) * invB * gg2[1].y + bt2[1].y;
            hi.x = (C[2][2] - meanB) * invB * gg2[2].x + bt2[2].x;
            hi.y = (C[2][3] - meanB) * invB * gg2[2].y + bt2[2].y;
            hi.z = (C[3][2] - meanB) * invB * gg2[3].x + bt2[3].x;
            hi.w = (C[3][3] - meanB) * invB * gg2[3].y + bt2[3].y;
            float* dst = hE + (size_t)eB * 128 + colb;
            *reinterpret_cast<float4*>(dst)     = lo;
            *reinterpret_cast<float4*>(dst + 4) = hi;
        }
    }
}

// ---------------------------------------------------------------------------
extern "C" void kernel_launch(void* const* d_in, const int* in_sizes, int n_in,
                              void* d_out, int out_size)
{
    const float* X    = (const float*)d_in[0];
    const int*   bat  = (const int*)d_in[1];
    const int*   ei   = (const int*)d_in[2];
    const float* Wn   = (const float*)d_in[3];
    const float* bn   = (const float*)d_in[4];
    const float* gn   = (const float*)d_in[5];
    const float* btn  = (const float*)d_in[6];
    const float* We   = (const float*)d_in[7];
    const float* be   = (const float*)d_in[8];
    const float* ge   = (const float*)d_in[9];
    const float* bte  = (const float*)d_in[10];

    int N = in_sizes[0] / 3;
    int E = in_sizes[2] / 2;

    float* hV = (float*)d_out;
    float* hE = hV + (size_t)N * 128;

    k_prep_Bfrag<<<5, 512>>>(We, be);
    k_node_geom<<<(N + 255) / 256, 256>>>(X, bat, N);
    k_node_out<<<(N * 32 + 255) / 256, 256>>>(Wn, bn, gn, btn, hV, N);
    k_edge_fused<<<(E + 127) / 128, 128>>>(ei, E, ge, bte, hE);
}

// round 9
// speedup vs baseline: 2.4873x; 1.1107x over previous
#include <cuda_runtime.h>
#include <cuda_fp16.h>
#include <math.h>
#include <stdint.h>

#define NMAX 100000

// Scratch (module-static):
__device__ float4 g_qn[NMAX * 2];      // per-node: [0]=frame quaternion, [1]=(X, valid)
__device__ float4 g_nf[NMAX];          // per-node 4 features
__device__ unsigned long long gBfrag[1536]; // B fragments [s(3)][j(16)][lane(32)]

struct F3 { float x, y, z; };
__device__ __forceinline__ F3 mk3(float a, float b, float c) { F3 r; r.x = a; r.y = b; r.z = c; return r; }
__device__ __forceinline__ F3 sub3(F3 a, F3 b) { return mk3(a.x - b.x, a.y - b.y, a.z - b.z); }
__device__ __forceinline__ float dot3(F3 a, F3 b) { return a.x * b.x + a.y * b.y + a.z * b.z; }
__device__ __forceinline__ F3 cross3(F3 a, F3 b) {
    return mk3(a.y * b.z - a.z * b.y, a.z * b.x - a.x * b.z, a.x * b.y - a.y * b.x);
}
__device__ __forceinline__ F3 nrm3(F3 a) {
    float n = sqrtf(dot3(a, a));
    float s = 1.0f / fmaxf(n, 1e-12f);
    return mk3(a.x * s, a.y * s, a.z * s);
}
__device__ __forceinline__ float signf_(float x) { return (float)((x > 0.0f) - (x < 0.0f)); }

__device__ __forceinline__ uint32_t smem_u32(const void* p) {
    uint32_t a;
    asm("{ .reg .u64 t; cvta.to.shared.u64 t, %1; cvt.u32.u64 %0, t; }" : "=r"(a) : "l"(p));
    return a;
}
__device__ __forceinline__ void mma16816h(float* c, uint32_t a0, uint32_t a1, uint32_t a2, uint32_t a3,
                                          uint32_t b0, uint32_t b1) {
    asm volatile(
        "mma.sync.aligned.m16n8k16.row.col.f32.f16.f16.f32 "
        "{%0,%1,%2,%3}, {%4,%5,%6,%7}, {%8,%9}, {%0,%1,%2,%3};"
        : "+f"(c[0]), "+f"(c[1]), "+f"(c[2]), "+f"(c[3])
        : "r"(a0), "r"(a1), "r"(a2), "r"(a3), "r"(b0), "r"(b1));
}
__device__ __forceinline__ void ldmatrix_x4(uint32_t& a0, uint32_t& a1, uint32_t& a2, uint32_t& a3, uint32_t addr) {
    asm volatile("ldmatrix.sync.aligned.m8n8.x4.shared.b16 {%0,%1,%2,%3}, [%4];"
                 : "=r"(a0), "=r"(a1), "=r"(a2), "=r"(a3) : "r"(addr));
}
__device__ __forceinline__ float h16rt(float x) {   // round-trip through fp16
    return __half2float(__float2half(x));
}
__device__ __forceinline__ uint32_t packh2(float a, float b) {
    __half2 p = __floats2half2_rn(a, b);
    return *reinterpret_cast<uint32_t*>(&p);
}

// ---------------------------------------------------------------------------
// Kernel 1: per-node geometry -> node feats + frame quaternion record
// ---------------------------------------------------------------------------
__global__ void k_node_geom(const float* __restrict__ X, const int* __restrict__ batch, int N)
{
    int i = blockIdx.x * blockDim.x + threadIdx.x;
    if (i >= N) return;

    auto ldx = [&](int j) -> F3 {
        j = j < 0 ? 0 : (j > N - 1 ? N - 1 : j);
        return mk3(X[3 * j], X[3 * j + 1], X[3 * j + 2]);
    };
    F3 xm1 = ldx(i - 1), x0 = ldx(i), xp1 = ldx(i + 1), xp2 = ldx(i + 2);

    int bi   = (i > 0)     && (batch[i] != batch[i - 1]);
    int bip1 = (i + 1 < N) && (batch[i + 1] != batch[i]);
    int bip2 = (i + 2 < N) && (batch[i + 2] != batch[i + 1]);
    bool bad_a = bi || bip1 || (i == 0) || (i == N - 1);
    bool bad_d = bi || bip1 || bip2 || (i == 0) || (i >= N - 2);

    F3 Um = nrm3(sub3(x0,  xm1));
    F3 Uc = nrm3(sub3(xp1, x0));
    F3 Up = nrm3(sub3(xp2, xp1));

    F3 c1 = nrm3(cross3(Um, Uc));
    F3 c2 = nrm3(cross3(Uc, Up));
    float cosd = fminf(fmaxf(dot3(c1, c2), -1.0f + 1e-6f), 1.0f - 1e-6f);
    float sg = signf_(dot3(c2, Um));
    float sdih = sg * sqrtf(fmaxf(1.0f - cosd * cosd, 0.0f));
    float cdih = (sg == 0.0f) ? 1.0f : cosd;

    F3 d0 = nrm3(sub3(xm1, x0));
    F3 d1 = nrm3(sub3(xp1, x0));
    float cosa = dot3(d0, d1);
    float sina = sqrtf(1.0f - cosa * cosa + 1e-6f);

    float4 nf;
    nf.x = bad_d ? 0.0f : sdih;
    nf.y = bad_d ? 0.0f : cdih;
    nf.z = bad_a ? 0.0f : sina;
    nf.w = bad_a ? 0.0f : cosa;
    g_nf[i] = nf;

    // Local frame Q = [bv nv cv] (columns); convert to quaternion (Shepperd).
    F3 bv = nrm3(sub3(Um, Uc));
    F3 nv = nrm3(cross3(Um, Uc));
    F3 cv = cross3(bv, nv);

    float qx = 0.0f, qy = 0.0f, qz = 0.0f, qw = 1.0f;
    if (!bad_a) {
        float m00 = bv.x, m10 = bv.y, m20 = bv.z;
        float m01 = nv.x, m11 = nv.y, m21 = nv.z;
        float m02 = cv.x, m12 = cv.y, m22 = cv.z;
        float tr = m00 + m11 + m22;
        if (tr > 0.0f) {
            float S = sqrtf(fmaxf(tr + 1.0f, 0.0f)) * 2.0f;
            S = fmaxf(S, 1e-20f);
            qw = 0.25f * S;
            qx = (m21 - m12) / S;
            qy = (m02 - m20) / S;
            qz = (m10 - m01) / S;
        } else if (m00 >= m11 && m00 >= m22) {
            float S = sqrtf(fmaxf(1.0f + m00 - m11 - m22, 0.0f)) * 2.0f;
            S = fmaxf(S, 1e-20f);
            qw = (m21 - m12) / S;
            qx = 0.25f * S;
            qy = (m01 + m10) / S;
            qz = (m02 + m20) / S;
        } else if (m11 >= m22) {
            float S = sqrtf(fmaxf(1.0f + m11 - m00 - m22, 0.0f)) * 2.0f;
            S = fmaxf(S, 1e-20f);
            qw = (m02 - m20) / S;
            qx = (m01 + m10) / S;
            qy = 0.25f * S;
            qz = (m12 + m21) / S;
        } else {
            float S = sqrtf(fmaxf(1.0f + m22 - m00 - m11, 0.0f)) * 2.0f;
            S = fmaxf(S, 1e-20f);
            qw = (m10 - m01) / S;
            qx = (m02 + m20) / S;
            qy = (m12 + m21) / S;
            qz = 0.25f * S;
        }
        float nq = rsqrtf(fmaxf(qx * qx + qy * qy + qz * qz + qw * qw, 1e-24f));
        qx *= nq; qy *= nq; qz *= nq; qw *= nq;
    }
    g_qn[i * 2 + 0] = make_float4(qx, qy, qz, qw);
    g_qn[i * 2 + 1] = make_float4(x0.x, x0.y, x0.z, bad_a ? 0.0f : 1.0f);
}

// ---------------------------------------------------------------------------
// Warp LayerNorm helper (node path)
// ---------------------------------------------------------------------------
__device__ __forceinline__ void ln_store(float4 a, float4 gg, float4 bt, float* __restrict__ dst)
{
    float s1 = a.x + a.y + a.z + a.w;
    float s2 = a.x * a.x + a.y * a.y + a.z * a.z + a.w * a.w;
#pragma unroll
    for (int o = 16; o > 0; o >>= 1) {
        s1 += __shfl_xor_sync(0xffffffffu, s1, o);
        s2 += __shfl_xor_sync(0xffffffffu, s2, o);
    }
    float mean = s1 * (1.0f / 128.0f);
    float var  = fmaxf(s2 * (1.0f / 128.0f) - mean * mean, 0.0f);
    float inv  = rsqrtf(var + 1e-5f);
    float4 o4;
    o4.x = (a.x - mean) * inv * gg.x + bt.x;
    o4.y = (a.y - mean) * inv * gg.y + bt.y;
    o4.z = (a.z - mean) * inv * gg.z + bt.z;
    o4.w = (a.w - mean) * inv * gg.w + bt.w;
    *reinterpret_cast<float4*>(dst) = o4;
}

// ---------------------------------------------------------------------------
// Kernel 2: h_V, 1 warp per node
// ---------------------------------------------------------------------------
__global__ void k_node_out(const float* __restrict__ Wn, const float* __restrict__ bn,
                           const float* __restrict__ gn, const float* __restrict__ bet,
                           float* __restrict__ hV, int N)
{
    int gw   = (blockIdx.x * blockDim.x + threadIdx.x) >> 5;
    int lane = threadIdx.x & 31;
    if (gw >= N) return;
    int c = 4 * lane;
    float4 w0 = *reinterpret_cast<const float4*>(Wn + 0 * 128 + c);
    float4 w1 = *reinterpret_cast<const float4*>(Wn + 1 * 128 + c);
    float4 w2 = *reinterpret_cast<const float4*>(Wn + 2 * 128 + c);
    float4 w3 = *reinterpret_cast<const float4*>(Wn + 3 * 128 + c);
    float4 bb = *reinterpret_cast<const float4*>(bn + c);
    float4 gg = *reinterpret_cast<const float4*>(gn + c);
    float4 bt = *reinterpret_cast<const float4*>(bet + c);

    float4 f = g_nf[gw];
    float4 a;
    a.x = bb.x + f.x * w0.x + f.y * w1.x + f.z * w2.x + f.w * w3.x;
    a.y = bb.y + f.x * w0.y + f.y * w1.y + f.z * w2.y + f.w * w3.y;
    a.z = bb.z + f.x * w0.z + f.y * w1.z + f.z * w2.z + f.w * w3.z;
    a.w = bb.w + f.x * w0.w + f.y * w1.w + f.z * w2.w + f.w * w3.w;
    ln_store(a, gg, bt, hV + (size_t)gw * 128 + c);
}

// ---------------------------------------------------------------------------
// Kernel 3-prep: fp16 B fragments for mma.m16n8k16 (run once, tiny).
// K' = 48 rows: 0..22 = f16(W), 23..45 = f16(W) (same; multiplies fl),
// 46 = f16(b), 47 = b - f16(b).   Dropped term: f * (W - f16(W)) ~ 2^-12.
// COLUMN PERMUTATION: B-frag col gid of tile (w,jj) holds physical weight
// column 32w + 8*(gid>>1) + 2*jj + (gid&1)  => lane owns 8 contiguous cols.
// ---------------------------------------------------------------------------
__global__ void k_prep_Bfrag(const float* __restrict__ We, const float* __restrict__ be)
{
    int idx = blockIdx.x * blockDim.x + threadIdx.x;
    if (idx >= 1536) return;
    int lane = idx & 31, j = (idx >> 5) & 15, s = idx >> 9;
    int gid = lane >> 2, tig = lane & 3;
    int w = j >> 2, jj = j & 3;
    int n = 32 * w + 8 * (gid >> 1) + 2 * jj + (gid & 1);

    auto wv = [&](int r) -> float {
        if (r < 23)  return h16rt(We[r * 128 + n]);
        if (r < 46)  return h16rt(We[(r - 23) * 128 + n]);
        if (r == 46) return h16rt(be[n]);
        if (r == 47) { float x = be[n]; return x - h16rt(x); }
        return 0.0f;
    };
    int k0 = 16 * s + 2 * tig;
    uint32_t b0 = packh2(wv(k0),     wv(k0 + 1));
    uint32_t b1 = packh2(wv(k0 + 8), wv(k0 + 9));
    gBfrag[idx] = ((unsigned long long)b1 << 32) | b0;
}

// ---------------------------------------------------------------------------
// Kernel 3: FUSED edge features (quaternion path) + fp16 tensor GEMM + LN.
// Block = 128 threads = 4 warps; tile = 128 edges; K' = 48 (3 k-steps).
// A row: cols 0..22 = f16(f), 23..45 = f - f16(f), 46..47 = 1, 48..55 = 0.
// ---------------------------------------------------------------------------
__global__ void __launch_bounds__(128, 6)
k_edge_fused(const int* __restrict__ ei, int E,
             const float* __restrict__ ge, const float* __restrict__ bet,
             float* __restrict__ hE)
{
    __shared__ __half A_img[128 * 56];   // stride 56 f16 = 112 B (conflict-free)
    __shared__ float2 red[2][16][5];

    int tid = threadIdx.x, w = tid >> 5, lane = tid & 31;
    int gid = lane >> 2, tig = lane & 3;
    int base = blockIdx.x * 128;

    // ---- Phase 1: per-thread edge features via quaternion composition ----
    {
        int e = base + tid;
        float f[23];
#pragma unroll
        for (int k = 0; k < 23; k++) f[k] = 0.0f;
        if (e < E) {
            int s = __ldg(ei + e);
            int t = __ldg(ei + E + e);

            float4 qt = g_qn[2 * t], xt = g_qn[2 * t + 1];
            float4 qs = g_qn[2 * s], xs = g_qn[2 * s + 1];

            float dvx = xs.x - xt.x, dvy = xs.y - xt.y, dvz = xs.z - xt.z;
            float d2   = dvx * dvx + dvy * dvy + dvz * dvz;
            float dist = sqrtf(d2 + 1e-6f);
            float rinv = 1.0f / fmaxf(sqrtf(d2), 1e-12f);
            float dhx = dvx * rinv, dhy = dvy * rinv, dhz = dvz * rinv;

            // q_rel = conj(q_t) * q_s
            float rw = qt.w * qs.w + qt.x * qs.x + qt.y * qs.y + qt.z * qs.z;
            float rx = qt.w * qs.x - qs.w * qt.x - (qt.y * qs.z - qt.z * qs.y);
            float ry = qt.w * qs.y - qs.w * qt.y - (qt.z * qs.x - qt.x * qs.z);
            float rz = qt.w * qs.z - qs.w * qt.z - (qt.x * qs.y - qt.y * qs.x);

            float sgnw = signf_(rw);
            float qn2 = rx * rx + ry * ry + rz * rz + rw * rw;
            float vm = (xt.w * xs.w) * sgnw / fmaxf(sqrtf(qn2), 1e-12f);
            f[0] = rx * vm; f[1] = ry * vm; f[2] = rz * vm; f[3] = rw * vm;

#pragma unroll
            for (int k = 0; k < 16; k++) {
                float mu = (float)k * (20.0f / 15.0f);
                float tt = (dist - mu) * 0.8f;
                f[4 + k] = __expf(-tt * tt);
            }

            // direct = rotate dhat by conj(q_t); mask by valid_t
            {
                float ax = qt.x, ay = qt.y, az = qt.z, aw = qt.w;
                float t1x = ay * dhz - az * dhy;
                float t1y = az * dhx - ax * dhz;
                float t1z = ax * dhy - ay * dhx;
                float ux = ay * t1z - az * t1y;
                float uy = az * t1x - ax * t1z;
                float uz = ax * t1y - ay * t1x;
                f[20] = (dhx - 2.0f * aw * t1x + 2.0f * ux) * xt.w;
                f[21] = (dhy - 2.0f * aw * t1y + 2.0f * uy) * xt.w;
                f[22] = (dhz - 2.0f * aw * t1z + 2.0f * uz) * xt.w;
            }
        }

        uint4* Av = reinterpret_cast<uint4*>(A_img + tid * 56);
#pragma unroll
        for (int g = 0; g < 7; g++) {
            uint32_t au[4];
#pragma unroll
            for (int h = 0; h < 4; h++) {
                int c0 = 8 * g + 2 * h, c1 = c0 + 1;
                float a0 = (c0 < 23) ? h16rt(f[c0])
                         : (c0 < 46) ? (f[c0 - 23] - h16rt(f[c0 - 23]))
                         : (c0 < 48) ? 1.0f : 0.0f;
                float a1 = (c1 < 23) ? h16rt(f[c1])
                         : (c1 < 46) ? (f[c1 - 23] - h16rt(f[c1 - 23]))
                         : (c1 < 48) ? 1.0f : 0.0f;
                au[h] = packh2(a0, a1);
            }
            Av[g] = make_uint4(au[0], au[1], au[2], au[3]);
        }
    }
    __syncthreads();

    // ---- B fragments + LN params ----
    uint32_t B0[3][4], B1[3][4];
#pragma unroll
    for (int s = 0; s < 3; s++)
#pragma unroll
        for (int jj = 0; jj < 4; jj++) {
            unsigned long long v = gBfrag[(s * 16 + (w * 4 + jj)) * 32 + lane];
            B0[s][jj] = (uint32_t)v;
            B1[s][jj] = (uint32_t)(v >> 32);
        }
    // lane's C[jj][0/1] = cols 32w + 8tig + 2jj + {0,1}
    float2 gg2[4], bt2[4];
#pragma unroll
    for (int jj = 0; jj < 4; jj++) {
        int colb = 32 * w + 8 * tig + 2 * jj;
        gg2[jj] = *reinterpret_cast<const float2*>(ge + colb);
        bt2[jj] = *reinterpret_cast<const float2*>(bet + colb);
    }

    uint32_t aBase = smem_u32(A_img)
                   + ((lane & 7) + ((lane & 8) ? 8 : 0)) * 112
                   + ((lane & 16) ? 16 : 0);

    // ---- Phase 2: 8 row-groups of 16 edges, one sync each ----
#pragma unroll 1
    for (int rg = 0; rg < 8; rg++) {
        int buf = rg & 1;
        float C[4][4];
#pragma unroll
        for (int jj = 0; jj < 4; jj++)
#pragma unroll
            for (int q = 0; q < 4; q++) C[jj][q] = 0.0f;

        uint32_t aAddr = aBase + rg * (16 * 112);
#pragma unroll
        for (int s = 0; s < 3; s++) {
            uint32_t a0, a1, a2, a3;
            ldmatrix_x4(a0, a1, a2, a3, aAddr + s * 32);
#pragma unroll
            for (int jj = 0; jj < 4; jj++)
                mma16816h(C[jj], a0, a1, a2, a3, B0[s][jj], B1[s][jj]);
        }

        float s1A = 0.f, s2A = 0.f, s1B = 0.f, s2B = 0.f;
#pragma unroll
        for (int jj = 0; jj < 4; jj++) {
            s1A += C[jj][0] + C[jj][1];
            s2A += C[jj][0] * C[jj][0] + C[jj][1] * C[jj][1];
            s1B += C[jj][2] + C[jj][3];
            s2B += C[jj][2] * C[jj][2] + C[jj][3] * C[jj][3];
        }
#pragma unroll
        for (int o = 1; o <= 2; o <<= 1) {
            s1A += __shfl_xor_sync(0xffffffffu, s1A, o);
            s2A += __shfl_xor_sync(0xffffffffu, s2A, o);
            s1B += __shfl_xor_sync(0xffffffffu, s1B, o);
            s2B += __shfl_xor_sync(0xffffffffu, s2B, o);
        }
        if (tig == 0) {
            red[buf][gid][w]     = make_float2(s1A, s2A);
            red[buf][gid + 8][w] = make_float2(s1B, s2B);
        }
        __syncthreads();

        float u1 = 0.f, u2 = 0.f, v1 = 0.f, v2 = 0.f;
#pragma unroll
        for (int ww = 0; ww < 4; ww++) {
            float2 a = red[buf][gid][ww];
            float2 b = red[buf][gid + 8][ww];
            u1 += a.x; u2 += a.y;
            v1 += b.x; v2 += b.y;
        }
        float meanA = u1 * (1.0f / 128.0f);
        float invA  = rsqrtf(fmaxf(u2 * (1.0f / 128.0f) - meanA * meanA, 0.0f) + 1e-5f);
        float meanB = v1 * (1.0f / 128.0f);
        float invB  = rsqrtf(fmaxf(v2 * (1.0f / 128.0f) - meanB * meanB, 0.0f) + 1e-5f);

        int eA = base + rg * 16 + gid, eB = eA + 8;
        int colb = 32 * w + 8 * tig;
        if (eA < E) {
            float4 lo, hi;
            lo.x = (C[0][0] - meanA) * invA * gg2[0].x + bt2[0].x;
            lo.y = (C[0][1] - meanA) * invA * gg2[0].y + bt2[0].y;
            lo.z = (C[1][0] - meanA) * invA * gg2[1].x + bt2[1].x;
            lo.w = (C[1][1] - meanA) * invA * gg2[1].y + bt2[1].y;
            hi.x = (C[2][0] - meanA) * invA * gg2[2].x + bt2[2].x;
            hi.y = (C[2][1] - meanA) * invA * gg2[2].y + bt2[2].y;
            hi.z = (C[3][0] - meanA) * invA * gg2[3].x + bt2[3].x;
            hi.w = (C[3][1] - meanA) * invA * gg2[3].y + bt2[3].y;
            float* dst = hE + (size_t)eA * 128 + colb;
            *reinterpret_cast<float4*>(dst)     = lo;
            *reinterpret_cast<float4*>(dst + 4) = hi;
        }
        if (eB < E) {
            float4 lo, hi;
            lo.x = (C[0][2] - meanB) * invB * gg2[0].x + bt2[0].x;
            lo.y = (C[0][3] - meanB) * invB * gg2[0].y + bt2[0].y;
            lo.z = (C[1][2] - meanB) * invB * gg2[1].x + bt2[1].x;
            lo.w = (C[1][3] - meanB) * invB * gg2[1].y + bt2[1].y;
            hi.x = (C[2][2] - meanB) * invB * gg2[2].x + bt2[2].x;
            hi.y = (C[2][3] - meanB) * invB * gg2[2].y + bt2[2].y;
            hi.z = (C[3][2] - meanB) * invB * gg2[3].x + bt2[3].x;
            hi.w = (C[3][3] - meanB) * invB * gg2[3].y + bt2[3].y;
            float* dst = hE + (size_t)eB * 128 + colb;
            *reinterpret_cast<float4*>(dst)     = lo;
            *reinterpret_cast<float4*>(dst + 4) = hi;
        }
    }
}

// ---------------------------------------------------------------------------
extern "C" void kernel_launch(void* const* d_in, const int* in_sizes, int n_in,
                              void* d_out, int out_size)
{
    const float* X    = (const float*)d_in[0];
    const int*   bat  = (const int*)d_in[1];
    const int*   ei   = (const int*)d_in[2];
    const float* Wn   = (const float*)d_in[3];
    const float* bn   = (const float*)d_in[4];
    const float* gn   = (const float*)d_in[5];
    const float* btn  = (const float*)d_in[6];
    const float* We   = (const float*)d_in[7];
    const float* be   = (const float*)d_in[8];
    const float* ge   = (const float*)d_in[9];
    const float* bte  = (const float*)d_in[10];

    int N = in_sizes[0] / 3;
    int E = in_sizes[2] / 2;

    float* hV = (float*)d_out;
    float* hE = hV + (size_t)N * 128;

    k_prep_Bfrag<<<3, 512>>>(We, be);
    k_node_geom<<<(N + 255) / 256, 256>>>(X, bat, N);
    k_node_out<<<(N * 32 + 255) / 256, 256>>>(Wn, bn, gn, btn, hV, N);
    k_edge_fused<<<(E + 127) / 128, 128>>>(ei, E, ge, bte, hE);
}

// round 10
// speedup vs baseline: 2.5214x; 1.0137x over previous
#include <cuda_runtime.h>
#include <cuda_fp16.h>
#include <math.h>
#include <stdint.h>

#define NMAX 100000

// Scratch (module-static):
__device__ float4 g_qn[NMAX * 2];      // per-node: [0]=frame quaternion, [1]=(X, valid)
__device__ unsigned long long gBfrag[1536]; // B fragments [s(3)][j(16)][lane(32)]

struct F3 { float x, y, z; };
__device__ __forceinline__ F3 mk3(float a, float b, float c) { F3 r; r.x = a; r.y = b; r.z = c; return r; }
__device__ __forceinline__ F3 sub3(F3 a, F3 b) { return mk3(a.x - b.x, a.y - b.y, a.z - b.z); }
__device__ __forceinline__ float dot3(F3 a, F3 b) { return a.x * b.x + a.y * b.y + a.z * b.z; }
__device__ __forceinline__ F3 cross3(F3 a, F3 b) {
    return mk3(a.y * b.z - a.z * b.y, a.z * b.x - a.x * b.z, a.x * b.y - a.y * b.x);
}
__device__ __forceinline__ F3 nrm3(F3 a) {
    float n = sqrtf(dot3(a, a));
    float s = 1.0f / fmaxf(n, 1e-12f);
    return mk3(a.x * s, a.y * s, a.z * s);
}
__device__ __forceinline__ float signf_(float x) { return (float)((x > 0.0f) - (x < 0.0f)); }

__device__ __forceinline__ uint32_t smem_u32(const void* p) {
    uint32_t a;
    asm("{ .reg .u64 t; cvta.to.shared.u64 t, %1; cvt.u32.u64 %0, t; }" : "=r"(a) : "l"(p));
    return a;
}
__device__ __forceinline__ void mma16816h(float* c, uint32_t a0, uint32_t a1, uint32_t a2, uint32_t a3,
                                          uint32_t b0, uint32_t b1) {
    asm volatile(
        "mma.sync.aligned.m16n8k16.row.col.f32.f16.f16.f32 "
        "{%0,%1,%2,%3}, {%4,%5,%6,%7}, {%8,%9}, {%0,%1,%2,%3};"
        : "+f"(c[0]), "+f"(c[1]), "+f"(c[2]), "+f"(c[3])
        : "r"(a0), "r"(a1), "r"(a2), "r"(a3), "r"(b0), "r"(b1));
}
__device__ __forceinline__ void ldmatrix_x4(uint32_t& a0, uint32_t& a1, uint32_t& a2, uint32_t& a3, uint32_t addr) {
    asm volatile("ldmatrix.sync.aligned.m8n8.x4.shared.b16 {%0,%1,%2,%3}, [%4];"
                 : "=r"(a0), "=r"(a1), "=r"(a2), "=r"(a3) : "r"(addr));
}
__device__ __forceinline__ float h16rt(float x) {   // round-trip through fp16
    return __half2float(__float2half(x));
}
__device__ __forceinline__ uint32_t packh2(float a, float b) {
    __half2 p = __floats2half2_rn(a, b);
    return *reinterpret_cast<uint32_t*>(&p);
}

// ---------------------------------------------------------------------------
// Fused node kernel: per-thread geometry -> smem; warp-per-node matmul + LN.
// Block = 256 threads = 8 warps; covers 256 nodes.
// ---------------------------------------------------------------------------
__global__ void __launch_bounds__(256)
k_node(const float* __restrict__ X, const int* __restrict__ batch, int N,
       const float* __restrict__ Wn, const float* __restrict__ bn,
       const float* __restrict__ gn, const float* __restrict__ bet,
       float* __restrict__ hV)
{
    __shared__ float4 s_nf[256];

    int tid = threadIdx.x, w = tid >> 5, lane = tid & 31;
    int base = blockIdx.x * 256;
    int i = base + tid;

    if (i < N) {
        auto ldx = [&](int j) -> F3 {
            j = j < 0 ? 0 : (j > N - 1 ? N - 1 : j);
            return mk3(X[3 * j], X[3 * j + 1], X[3 * j + 2]);
        };
        F3 xm1 = ldx(i - 1), x0 = ldx(i), xp1 = ldx(i + 1), xp2 = ldx(i + 2);

        int bi   = (i > 0)     && (batch[i] != batch[i - 1]);
        int bip1 = (i + 1 < N) && (batch[i + 1] != batch[i]);
        int bip2 = (i + 2 < N) && (batch[i + 2] != batch[i + 1]);
        bool bad_a = bi || bip1 || (i == 0) || (i == N - 1);
        bool bad_d = bi || bip1 || bip2 || (i == 0) || (i >= N - 2);

        F3 Um = nrm3(sub3(x0,  xm1));
        F3 Uc = nrm3(sub3(xp1, x0));
        F3 Up = nrm3(sub3(xp2, xp1));

        F3 c1 = nrm3(cross3(Um, Uc));
        F3 c2 = nrm3(cross3(Uc, Up));
        float cosd = fminf(fmaxf(dot3(c1, c2), -1.0f + 1e-6f), 1.0f - 1e-6f);
        float sg = signf_(dot3(c2, Um));
        float sdih = sg * sqrtf(fmaxf(1.0f - cosd * cosd, 0.0f));
        float cdih = (sg == 0.0f) ? 1.0f : cosd;

        F3 d0 = nrm3(sub3(xm1, x0));
        F3 d1 = nrm3(sub3(xp1, x0));
        float cosa = dot3(d0, d1);
        float sina = sqrtf(1.0f - cosa * cosa + 1e-6f);

        float4 nf;
        nf.x = bad_d ? 0.0f : sdih;
        nf.y = bad_d ? 0.0f : cdih;
        nf.z = bad_a ? 0.0f : sina;
        nf.w = bad_a ? 0.0f : cosa;
        s_nf[tid] = nf;

        // Local frame Q = [bv nv cv]; convert to quaternion (Shepperd).
        F3 bv = nrm3(sub3(Um, Uc));
        F3 nv = nrm3(cross3(Um, Uc));
        F3 cv = cross3(bv, nv);

        float qx = 0.0f, qy = 0.0f, qz = 0.0f, qw = 1.0f;
        if (!bad_a) {
            float m00 = bv.x, m10 = bv.y, m20 = bv.z;
            float m01 = nv.x, m11 = nv.y, m21 = nv.z;
            float m02 = cv.x, m12 = cv.y, m22 = cv.z;
            float tr = m00 + m11 + m22;
            if (tr > 0.0f) {
                float S = fmaxf(sqrtf(fmaxf(tr + 1.0f, 0.0f)) * 2.0f, 1e-20f);
                qw = 0.25f * S;
                qx = (m21 - m12) / S;
                qy = (m02 - m20) / S;
                qz = (m10 - m01) / S;
            } else if (m00 >= m11 && m00 >= m22) {
                float S = fmaxf(sqrtf(fmaxf(1.0f + m00 - m11 - m22, 0.0f)) * 2.0f, 1e-20f);
                qw = (m21 - m12) / S;
                qx = 0.25f * S;
                qy = (m01 + m10) / S;
                qz = (m02 + m20) / S;
            } else if (m11 >= m22) {
                float S = fmaxf(sqrtf(fmaxf(1.0f + m11 - m00 - m22, 0.0f)) * 2.0f, 1e-20f);
                qw = (m02 - m20) / S;
                qx = (m01 + m10) / S;
                qy = 0.25f * S;
                qz = (m12 + m21) / S;
            } else {
                float S = fmaxf(sqrtf(fmaxf(1.0f + m22 - m00 - m11, 0.0f)) * 2.0f, 1e-20f);
                qw = (m10 - m01) / S;
                qx = (m02 + m20) / S;
                qy = (m12 + m21) / S;
                qz = 0.25f * S;
            }
            float nq = rsqrtf(fmaxf(qx * qx + qy * qy + qz * qz + qw * qw, 1e-24f));
            qx *= nq; qy *= nq; qz *= nq; qw *= nq;
        }
        g_qn[i * 2 + 0] = make_float4(qx, qy, qz, qw);
        g_qn[i * 2 + 1] = make_float4(x0.x, x0.y, x0.z, bad_a ? 0.0f : 1.0f);
    } else {
        s_nf[tid] = make_float4(0.f, 0.f, 0.f, 0.f);
    }
    __syncthreads();

    // warp-per-node output: warp w handles local nodes 32w .. 32w+31
    int c = 4 * lane;
    float4 w0 = *reinterpret_cast<const float4*>(Wn + 0 * 128 + c);
    float4 w1 = *reinterpret_cast<const float4*>(Wn + 1 * 128 + c);
    float4 w2 = *reinterpret_cast<const float4*>(Wn + 2 * 128 + c);
    float4 w3 = *reinterpret_cast<const float4*>(Wn + 3 * 128 + c);
    float4 bb = *reinterpret_cast<const float4*>(bn + c);
    float4 gg = *reinterpret_cast<const float4*>(gn + c);
    float4 bt = *reinterpret_cast<const float4*>(bet + c);

#pragma unroll 1
    for (int it = 0; it < 32; it++) {
        int gw = base + 32 * w + it;
        if (gw >= N) break;
        float4 f = s_nf[32 * w + it];
        float4 a;
        a.x = bb.x + f.x * w0.x + f.y * w1.x + f.z * w2.x + f.w * w3.x;
        a.y = bb.y + f.x * w0.y + f.y * w1.y + f.z * w2.y + f.w * w3.y;
        a.z = bb.z + f.x * w0.z + f.y * w1.z + f.z * w2.z + f.w * w3.z;
        a.w = bb.w + f.x * w0.w + f.y * w1.w + f.z * w2.w + f.w * w3.w;

        float s1 = a.x + a.y + a.z + a.w;
        float s2 = a.x * a.x + a.y * a.y + a.z * a.z + a.w * a.w;
#pragma unroll
        for (int o = 16; o > 0; o >>= 1) {
            s1 += __shfl_xor_sync(0xffffffffu, s1, o);
            s2 += __shfl_xor_sync(0xffffffffu, s2, o);
        }
        float mean = s1 * (1.0f / 128.0f);
        float var  = fmaxf(s2 * (1.0f / 128.0f) - mean * mean, 0.0f);
        float inv  = rsqrtf(var + 1e-5f);
        float4 o4;
        o4.x = (a.x - mean) * inv * gg.x + bt.x;
        o4.y = (a.y - mean) * inv * gg.y + bt.y;
        o4.z = (a.z - mean) * inv * gg.z + bt.z;
        o4.w = (a.w - mean) * inv * gg.w + bt.w;
        __stcs(reinterpret_cast<float4*>(hV + (size_t)gw * 128 + c), o4);
    }
}

// ---------------------------------------------------------------------------
// Prep: fp16 B fragments for mma.m16n8k16 (run once, tiny).
// K' = 48 rows: 0..22 = f16(W), 23..45 = f16(W), 46 = f16(b), 47 = b - f16(b).
// Column permutation: B-frag col gid of tile (w,jj) = weight col
// 32w + 8*(gid>>1) + 2*jj + (gid&1)  => lane owns 8 contiguous output cols.
// ---------------------------------------------------------------------------
__global__ void k_prep_Bfrag(const float* __restrict__ We, const float* __restrict__ be)
{
    int idx = blockIdx.x * blockDim.x + threadIdx.x;
    if (idx >= 1536) return;
    int lane = idx & 31, j = (idx >> 5) & 15, s = idx >> 9;
    int gid = lane >> 2, tig = lane & 3;
    int w = j >> 2, jj = j & 3;
    int n = 32 * w + 8 * (gid >> 1) + 2 * jj + (gid & 1);

    auto wv = [&](int r) -> float {
        if (r < 23)  return h16rt(We[r * 128 + n]);
        if (r < 46)  return h16rt(We[(r - 23) * 128 + n]);
        if (r == 46) return h16rt(be[n]);
        if (r == 47) { float x = be[n]; return x - h16rt(x); }
        return 0.0f;
    };
    int k0 = 16 * s + 2 * tig;
    uint32_t b0 = packh2(wv(k0),     wv(k0 + 1));
    uint32_t b1 = packh2(wv(k0 + 8), wv(k0 + 9));
    gBfrag[idx] = ((unsigned long long)b1 << 32) | b0;
}

// ---------------------------------------------------------------------------
// FUSED edge features (quaternion path) + fp16 tensor GEMM + LN.
// Block = 128 threads = 4 warps; tile = 128 edges; K' = 48 (3 k-steps).
// ---------------------------------------------------------------------------
__global__ void __launch_bounds__(128, 7)
k_edge_fused(const int* __restrict__ ei, int E,
             const float* __restrict__ ge, const float* __restrict__ bet,
             float* __restrict__ hE)
{
    __shared__ __half A_img[128 * 56];   // stride 56 f16 = 112 B (conflict-free)
    __shared__ float2 red[2][16][5];

    int tid = threadIdx.x, w = tid >> 5, lane = tid & 31;
    int gid = lane >> 2, tig = lane & 3;
    int base = blockIdx.x * 128;

    // ---- Phase 1: per-thread edge features via quaternion composition ----
    {
        int e = base + tid;
        float f[23];
#pragma unroll
        for (int k = 0; k < 23; k++) f[k] = 0.0f;
        if (e < E) {
            int s = __ldg(ei + e);
            int t = __ldg(ei + E + e);

            float4 qt = g_qn[2 * t], xt = g_qn[2 * t + 1];
            float4 qs = g_qn[2 * s], xs = g_qn[2 * s + 1];

            float dvx = xs.x - xt.x, dvy = xs.y - xt.y, dvz = xs.z - xt.z;
            float d2   = dvx * dvx + dvy * dvy + dvz * dvz;
            float dist = sqrtf(d2 + 1e-6f);
            float rinv = 1.0f / fmaxf(sqrtf(d2), 1e-12f);
            float dhx = dvx * rinv, dhy = dvy * rinv, dhz = dvz * rinv;

            // q_rel = conj(q_t) * q_s
            float rw = qt.w * qs.w + qt.x * qs.x + qt.y * qs.y + qt.z * qs.z;
            float rx = qt.w * qs.x - qs.w * qt.x - (qt.y * qs.z - qt.z * qs.y);
            float ry = qt.w * qs.y - qs.w * qt.y - (qt.z * qs.x - qt.x * qs.z);
            float rz = qt.w * qs.z - qs.w * qt.z - (qt.x * qs.y - qt.y * qs.x);

            float sgnw = signf_(rw);
            float qn2 = rx * rx + ry * ry + rz * rz + rw * rw;
            float vm = (xt.w * xs.w) * sgnw / fmaxf(sqrtf(qn2), 1e-12f);
            f[0] = rx * vm; f[1] = ry * vm; f[2] = rz * vm; f[3] = rw * vm;

#pragma unroll
            for (int k = 0; k < 16; k++) {
                float mu = (float)k * (20.0f / 15.0f);
                float tt = (dist - mu) * 0.8f;
                f[4 + k] = __expf(-tt * tt);
            }

            // direct = rotate dhat by conj(q_t); mask by valid_t
            {
                float ax = qt.x, ay = qt.y, az = qt.z, aw = qt.w;
                float t1x = ay * dhz - az * dhy;
                float t1y = az * dhx - ax * dhz;
                float t1z = ax * dhy - ay * dhx;
                float ux = ay * t1z - az * t1y;
                float uy = az * t1x - ax * t1z;
                float uz = ax * t1y - ay * t1x;
                f[20] = (dhx - 2.0f * aw * t1x + 2.0f * ux) * xt.w;
                f[21] = (dhy - 2.0f * aw * t1y + 2.0f * uy) * xt.w;
                f[22] = (dhz - 2.0f * aw * t1z + 2.0f * uz) * xt.w;
            }
        }

        uint4* Av = reinterpret_cast<uint4*>(A_img + tid * 56);
#pragma unroll
        for (int g = 0; g < 7; g++) {
            uint32_t au[4];
#pragma unroll
            for (int h = 0; h < 4; h++) {
                int c0 = 8 * g + 2 * h, c1 = c0 + 1;
                float a0 = (c0 < 23) ? h16rt(f[c0])
                         : (c0 < 46) ? (f[c0 - 23] - h16rt(f[c0 - 23]))
                         : (c0 < 48) ? 1.0f : 0.0f;
                float a1 = (c1 < 23) ? h16rt(f[c1])
                         : (c1 < 46) ? (f[c1 - 23] - h16rt(f[c1 - 23]))
                         : (c1 < 48) ? 1.0f : 0.0f;
                au[h] = packh2(a0, a1);
            }
            Av[g] = make_uint4(au[0], au[1], au[2], au[3]);
        }
    }
    __syncthreads();

    // ---- B fragments + LN params ----
    uint32_t B0[3][4], B1[3][4];
#pragma unroll
    for (int s = 0; s < 3; s++)
#pragma unroll
        for (int jj = 0; jj < 4; jj++) {
            unsigned long long v = gBfrag[(s * 16 + (w * 4 + jj)) * 32 + lane];
            B0[s][jj] = (uint32_t)v;
            B1[s][jj] = (uint32_t)(v >> 32);
        }
    float2 gg2[4], bt2[4];
#pragma unroll
    for (int jj = 0; jj < 4; jj++) {
        int colb = 32 * w + 8 * tig + 2 * jj;
        gg2[jj] = *reinterpret_cast<const float2*>(ge + colb);
        bt2[jj] = *reinterpret_cast<const float2*>(bet + colb);
    }

    uint32_t aBase = smem_u32(A_img)
                   + ((lane & 7) + ((lane & 8) ? 8 : 0)) * 112
                   + ((lane & 16) ? 16 : 0);

    // ---- Phase 2: 8 row-groups of 16 edges, one sync each ----
#pragma unroll 1
    for (int rg = 0; rg < 8; rg++) {
        int buf = rg & 1;
        float C[4][4];
#pragma unroll
        for (int jj = 0; jj < 4; jj++)
#pragma unroll
            for (int q = 0; q < 4; q++) C[jj][q] = 0.0f;

        uint32_t aAddr = aBase + rg * (16 * 112);
#pragma unroll
        for (int s = 0; s < 3; s++) {
            uint32_t a0, a1, a2, a3;
            ldmatrix_x4(a0, a1, a2, a3, aAddr + s * 32);
#pragma unroll
            for (int jj = 0; jj < 4; jj++)
                mma16816h(C[jj], a0, a1, a2, a3, B0[s][jj], B1[s][jj]);
        }

        float s1A = 0.f, s2A = 0.f, s1B = 0.f, s2B = 0.f;
#pragma unroll
        for (int jj = 0; jj < 4; jj++) {
            s1A += C[jj][0] + C[jj][1];
            s2A += C[jj][0] * C[jj][0] + C[jj][1] * C[jj][1];
            s1B += C[jj][2] + C[jj][3];
            s2B += C[jj][2] * C[jj][2] + C[jj][3] * C[jj][3];
        }
#pragma unroll
        for (int o = 1; o <= 2; o <<= 1) {
            s1A += __shfl_xor_sync(0xffffffffu, s1A, o);
            s2A += __shfl_xor_sync(0xffffffffu, s2A, o);
            s1B += __shfl_xor_sync(0xffffffffu, s1B, o);
            s2B += __shfl_xor_sync(0xffffffffu, s2B, o);
        }
        if (tig == 0) {
            red[buf][gid][w]     = make_float2(s1A, s2A);
            red[buf][gid + 8][w] = make_float2(s1B, s2B);
        }
        __syncthreads();

        float u1 = 0.f, u2 = 0.f, v1 = 0.f, v2 = 0.f;
#pragma unroll
        for (int ww = 0; ww < 4; ww++) {
            float2 a = red[buf][gid][ww];
            float2 b = red[buf][gid + 8][ww];
            u1 += a.x; u2 += a.y;
            v1 += b.x; v2 += b.y;
        }
        float meanA = u1 * (1.0f / 128.0f);
        float invA  = rsqrtf(fmaxf(u2 * (1.0f / 128.0f) - meanA * meanA, 0.0f) + 1e-5f);
        float meanB = v1 * (1.0f / 128.0f);
        float invB  = rsqrtf(fmaxf(v2 * (1.0f / 128.0f) - meanB * meanB, 0.0f) + 1e-5f);

        int eA = base + rg * 16 + gid, eB = eA + 8;
        int colb = 32 * w + 8 * tig;
        if (eA < E) {
            float4 lo, hi;
            lo.x = (C[0][0] - meanA) * invA * gg2[0].x + bt2[0].x;
            lo.y = (C[0][1] - meanA) * invA * gg2[0].y + bt2[0].y;
            lo.z = (C[1][0] - meanA) * invA * gg2[1].x + bt2[1].x;
            lo.w = (C[1][1] - meanA) * invA * gg2[1].y + bt2[1].y;
            hi.x = (C[2][0] - meanA) * invA * gg2[2].x + bt2[2].x;
            hi.y = (C[2][1] - meanA) * invA * gg2[2].y + bt2[2].y;
            hi.z = (C[3][0] - meanA) * invA * gg2[3].x + bt2[3].x;
            hi.w = (C[3][1] - meanA) * invA * gg2[3].y + bt2[3].y;
            float* dst = hE + (size_t)eA * 128 + colb;
            __stcs(reinterpret_cast<float4*>(dst),     lo);
            __stcs(reinterpret_cast<float4*>(dst + 4), hi);
        }
        if (eB < E) {
            float4 lo, hi;
            lo.x = (C[0][2] - meanB) * invB * gg2[0].x + bt2[0].x;
            lo.y = (C[0][3] - meanB) * invB * gg2[0].y + bt2[0].y;
            lo.z = (C[1][2] - meanB) * invB * gg2[1].x + bt2[1].x;
            lo.w = (C[1][3] - meanB) * invB * gg2[1].y + bt2[1].y;
            hi.x = (C[2][2] - meanB) * invB * gg2[2].x + bt2[2].x;
            hi.y = (C[2][3] - meanB) * invB * gg2[2].y + bt2[2].y;
            hi.z = (C[3][2] - meanB) * invB * gg2[3].x + bt2[3].x;
            hi.w = (C[3][3] - meanB) * invB * gg2[3].y + bt2[3].y;
            float* dst = hE + (size_t)eB * 128 + colb;
            __stcs(reinterpret_cast<float4*>(dst),     lo);
            __stcs(reinterpret_cast<float4*>(dst + 4), hi);
        }
    }
}

// ---------------------------------------------------------------------------
extern "C" void kernel_launch(void* const* d_in, const int* in_sizes, int n_in,
                              void* d_out, int out_size)
{
    const float* X    = (const float*)d_in[0];
    const int*   bat  = (const int*)d_in[1];
    const int*   ei   = (const int*)d_in[2];
    const float* Wn   = (const float*)d_in[3];
    const float* bn   = (const float*)d_in[4];
    const float* gn   = (const float*)d_in[5];
    const float* btn  = (const float*)d_in[6];
    const float* We   = (const float*)d_in[7];
    const float* be   = (const float*)d_in[8];
    const float* ge   = (const float*)d_in[9];
    const float* bte  = (const float*)d_in[10];

    int N = in_sizes[0] / 3;
    int E = in_sizes[2] / 2;

    float* hV = (float*)d_out;
    float* hE = hV + (size_t)N * 128;

    k_prep_Bfrag<<<3, 512>>>(We, be);
    k_node<<<(N + 255) / 256, 256>>>(X, bat, N, Wn, bn, gn, btn, hV);
    k_edge_fused<<<(E + 127) / 128, 128>>>(ei, E, ge, bte, hE);
}

// round 11
// speedup vs baseline: 2.5952x; 1.0292x over previous
#include <cuda_runtime.h>
#include <cuda_fp16.h>
#include <math.h>
#include <stdint.h>

#define NMAX 100000

// Scratch (module-static):
__device__ float4 g_qn[NMAX * 2];      // per-node: [0]=frame quaternion, [1]=(X, valid)
__device__ unsigned long long gBfrag[1536]; // B fragments [s(3)][j(16)][lane(32)]

struct F3 { float x, y, z; };
__device__ __forceinline__ F3 mk3(float a, float b, float c) { F3 r; r.x = a; r.y = b; r.z = c; return r; }
__device__ __forceinline__ F3 sub3(F3 a, F3 b) { return mk3(a.x - b.x, a.y - b.y, a.z - b.z); }
__device__ __forceinline__ float dot3(F3 a, F3 b) { return a.x * b.x + a.y * b.y + a.z * b.z; }
__device__ __forceinline__ F3 cross3(F3 a, F3 b) {
    return mk3(a.y * b.z - a.z * b.y, a.z * b.x - a.x * b.z, a.x * b.y - a.y * b.x);
}
__device__ __forceinline__ F3 nrm3(F3 a) {
    float n = sqrtf(dot3(a, a));
    float s = 1.0f / fmaxf(n, 1e-12f);
    return mk3(a.x * s, a.y * s, a.z * s);
}
__device__ __forceinline__ float signf_(float x) { return (float)((x > 0.0f) - (x < 0.0f)); }

__device__ __forceinline__ uint32_t smem_u32(const void* p) {
    uint32_t a;
    asm("{ .reg .u64 t; cvta.to.shared.u64 t, %1; cvt.u32.u64 %0, t; }" : "=r"(a) : "l"(p));
    return a;
}
__device__ __forceinline__ void mma16816h(float* c, uint32_t a0, uint32_t a1, uint32_t a2, uint32_t a3,
                                          uint32_t b0, uint32_t b1) {
    asm volatile(
        "mma.sync.aligned.m16n8k16.row.col.f32.f16.f16.f32 "
        "{%0,%1,%2,%3}, {%4,%5,%6,%7}, {%8,%9}, {%0,%1,%2,%3};"
        : "+f"(c[0]), "+f"(c[1]), "+f"(c[2]), "+f"(c[3])
        : "r"(a0), "r"(a1), "r"(a2), "r"(a3), "r"(b0), "r"(b1));
}
__device__ __forceinline__ void ldmatrix_x4(uint32_t& a0, uint32_t& a1, uint32_t& a2, uint32_t& a3, uint32_t addr) {
    asm volatile("ldmatrix.sync.aligned.m8n8.x4.shared.b16 {%0,%1,%2,%3}, [%4];"
                 : "=r"(a0), "=r"(a1), "=r"(a2), "=r"(a3) : "r"(addr));
}
__device__ __forceinline__ float h16rt(float x) {   // round-trip through fp16
    return __half2float(__float2half(x));
}
__device__ __forceinline__ uint32_t packh2(float a, float b) {
    __half2 p = __floats2half2_rn(a, b);
    return *reinterpret_cast<uint32_t*>(&p);
}

// ---------------------------------------------------------------------------
// Fused node kernel: per-thread geometry -> smem; warp-per-node matmul + LN.
// Block 0 additionally builds the fp16 B fragments for the edge GEMM.
// Block = 256 threads = 8 warps; covers 256 nodes.
// ---------------------------------------------------------------------------
__global__ void __launch_bounds__(256)
k_node(const float* __restrict__ X, const int* __restrict__ batch, int N,
       const float* __restrict__ Wn, const float* __restrict__ bn,
       const float* __restrict__ gn, const float* __restrict__ bet,
       const float* __restrict__ We, const float* __restrict__ be,
       float* __restrict__ hV)
{
    __shared__ float4 s_nf[256];

    int tid = threadIdx.x, w = tid >> 5, lane = tid & 31;
    int base = blockIdx.x * 256;
    int i = base + tid;

    // ---- block 0: build B fragments (K'=48) for the edge GEMM ----
    // idx layout: [s(3)][j(16)][lane(32)]; j = 4*warpSlice + jj.
    // Column permutation: frag col gid of tile (w,jj) = weight col
    // 32w + 8*(gid>>1) + 2*jj + (gid&1).
    if (blockIdx.x == 0) {
#pragma unroll
        for (int u = 0; u < 6; u++) {
            int idx = tid + 256 * u;   // 6*256 = 1536
            int fl = idx & 31, j = (idx >> 5) & 15, s = idx >> 9;
            int fgid = fl >> 2, ftig = fl & 3;
            int fw = j >> 2, fjj = j & 3;
            int n = 32 * fw + 8 * (fgid >> 1) + 2 * fjj + (fgid & 1);
            auto wv = [&](int r) -> float {
                if (r < 23)  return h16rt(We[r * 128 + n]);
                if (r < 46)  return h16rt(We[(r - 23) * 128 + n]);
                if (r == 46) return h16rt(be[n]);
                if (r == 47) { float x = be[n]; return x - h16rt(x); }
                return 0.0f;
            };
            int k0 = 16 * s + 2 * ftig;
            uint32_t b0 = packh2(wv(k0),     wv(k0 + 1));
            uint32_t b1 = packh2(wv(k0 + 8), wv(k0 + 9));
            gBfrag[idx] = ((unsigned long long)b1 << 32) | b0;
        }
    }

    if (i < N) {
        auto ldx = [&](int j) -> F3 {
            j = j < 0 ? 0 : (j > N - 1 ? N - 1 : j);
            return mk3(X[3 * j], X[3 * j + 1], X[3 * j + 2]);
        };
        F3 xm1 = ldx(i - 1), x0 = ldx(i), xp1 = ldx(i + 1), xp2 = ldx(i + 2);

        int bi   = (i > 0)     && (batch[i] != batch[i - 1]);
        int bip1 = (i + 1 < N) && (batch[i + 1] != batch[i]);
        int bip2 = (i + 2 < N) && (batch[i + 2] != batch[i + 1]);
        bool bad_a = bi || bip1 || (i == 0) || (i == N - 1);
        bool bad_d = bi || bip1 || bip2 || (i == 0) || (i >= N - 2);

        F3 Um = nrm3(sub3(x0,  xm1));
        F3 Uc = nrm3(sub3(xp1, x0));
        F3 Up = nrm3(sub3(xp2, xp1));

        F3 c1 = nrm3(cross3(Um, Uc));
        F3 c2 = nrm3(cross3(Uc, Up));
        float cosd = fminf(fmaxf(dot3(c1, c2), -1.0f + 1e-6f), 1.0f - 1e-6f);
        float sg = signf_(dot3(c2, Um));
        float sdih = sg * sqrtf(fmaxf(1.0f - cosd * cosd, 0.0f));
        float cdih = (sg == 0.0f) ? 1.0f : cosd;

        F3 d0 = nrm3(sub3(xm1, x0));
        F3 d1 = nrm3(sub3(xp1, x0));
        float cosa = dot3(d0, d1);
        float sina = sqrtf(1.0f - cosa * cosa + 1e-6f);

        float4 nf;
        nf.x = bad_d ? 0.0f : sdih;
        nf.y = bad_d ? 0.0f : cdih;
        nf.z = bad_a ? 0.0f : sina;
        nf.w = bad_a ? 0.0f : cosa;
        s_nf[tid] = nf;

        // Local frame Q = [bv nv cv]; convert to quaternion (Shepperd).
        F3 bv = nrm3(sub3(Um, Uc));
        F3 nv = nrm3(cross3(Um, Uc));
        F3 cv = cross3(bv, nv);

        float qx = 0.0f, qy = 0.0f, qz = 0.0f, qw = 1.0f;
        if (!bad_a) {
            float m00 = bv.x, m10 = bv.y, m20 = bv.z;
            float m01 = nv.x, m11 = nv.y, m21 = nv.z;
            float m02 = cv.x, m12 = cv.y, m22 = cv.z;
            float tr = m00 + m11 + m22;
            if (tr > 0.0f) {
                float S = fmaxf(sqrtf(fmaxf(tr + 1.0f, 0.0f)) * 2.0f, 1e-20f);
                qw = 0.25f * S;
                qx = (m21 - m12) / S;
                qy = (m02 - m20) / S;
                qz = (m10 - m01) / S;
            } else if (m00 >= m11 && m00 >= m22) {
                float S = fmaxf(sqrtf(fmaxf(1.0f + m00 - m11 - m22, 0.0f)) * 2.0f, 1e-20f);
                qw = (m21 - m12) / S;
                qx = 0.25f * S;
                qy = (m01 + m10) / S;
                qz = (m02 + m20) / S;
            } else if (m11 >= m22) {
                float S = fmaxf(sqrtf(fmaxf(1.0f + m11 - m00 - m22, 0.0f)) * 2.0f, 1e-20f);
                qw = (m02 - m20) / S;
                qx = (m01 + m10) / S;
                qy = 0.25f * S;
                qz = (m12 + m21) / S;
            } else {
                float S = fmaxf(sqrtf(fmaxf(1.0f + m22 - m00 - m11, 0.0f)) * 2.0f, 1e-20f);
                qw = (m10 - m01) / S;
                qx = (m02 + m20) / S;
                qy = (m12 + m21) / S;
                qz = 0.25f * S;
            }
            float nq = rsqrtf(fmaxf(qx * qx + qy * qy + qz * qz + qw * qw, 1e-24f));
            qx *= nq; qy *= nq; qz *= nq; qw *= nq;
        }
        g_qn[i * 2 + 0] = make_float4(qx, qy, qz, qw);
        g_qn[i * 2 + 1] = make_float4(x0.x, x0.y, x0.z, bad_a ? 0.0f : 1.0f);
    } else {
        s_nf[tid] = make_float4(0.f, 0.f, 0.f, 0.f);
    }
    __syncthreads();

    // warp-per-node output: warp w handles local nodes 32w .. 32w+31
    int c = 4 * lane;
    float4 w0 = *reinterpret_cast<const float4*>(Wn + 0 * 128 + c);
    float4 w1 = *reinterpret_cast<const float4*>(Wn + 1 * 128 + c);
    float4 w2 = *reinterpret_cast<const float4*>(Wn + 2 * 128 + c);
    float4 w3 = *reinterpret_cast<const float4*>(Wn + 3 * 128 + c);
    float4 bb = *reinterpret_cast<const float4*>(bn + c);
    float4 gg = *reinterpret_cast<const float4*>(gn + c);
    float4 bt = *reinterpret_cast<const float4*>(bet + c);

#pragma unroll 1
    for (int it = 0; it < 32; it++) {
        int gw = base + 32 * w + it;
        if (gw >= N) break;
        float4 f = s_nf[32 * w + it];
        float4 a;
        a.x = bb.x + f.x * w0.x + f.y * w1.x + f.z * w2.x + f.w * w3.x;
        a.y = bb.y + f.x * w0.y + f.y * w1.y + f.z * w2.y + f.w * w3.y;
        a.z = bb.z + f.x * w0.z + f.y * w1.z + f.z * w2.z + f.w * w3.z;
        a.w = bb.w + f.x * w0.w + f.y * w1.w + f.z * w2.w + f.w * w3.w;

        float s1 = a.x + a.y + a.z + a.w;
        float s2 = a.x * a.x + a.y * a.y + a.z * a.z + a.w * a.w;
#pragma unroll
        for (int o = 16; o > 0; o >>= 1) {
            s1 += __shfl_xor_sync(0xffffffffu, s1, o);
            s2 += __shfl_xor_sync(0xffffffffu, s2, o);
        }
        float mean = s1 * (1.0f / 128.0f);
        float var  = fmaxf(s2 * (1.0f / 128.0f) - mean * mean, 0.0f);
        float inv  = rsqrtf(var + 1e-5f);
        float4 o4;
        o4.x = (a.x - mean) * inv * gg.x + bt.x;
        o4.y = (a.y - mean) * inv * gg.y + bt.y;
        o4.z = (a.z - mean) * inv * gg.z + bt.z;
        o4.w = (a.w - mean) * inv * gg.w + bt.w;
        __stcs(reinterpret_cast<float4*>(hV + (size_t)gw * 128 + c), o4);
    }
}

// ---------------------------------------------------------------------------
// FUSED edge features (quaternion path) + fp16 tensor GEMM + LN.
// Block = 128 threads = 4 warps; tile = 128 edges; K' = 48 (3 k-steps).
// A row: cols 0..22 = f16(f), 23..45 = f - f16(f), 46..47 = 1, 48..55 = 0.
// ---------------------------------------------------------------------------
__global__ void __launch_bounds__(128, 7)
k_edge_fused(const int* __restrict__ ei, int E,
             const float* __restrict__ ge, const float* __restrict__ bet,
             float* __restrict__ hE)
{
    __shared__ __half A_img[128 * 56];   // stride 56 f16 = 112 B (conflict-free)
    __shared__ float2 red[2][16][5];

    int tid = threadIdx.x, w = tid >> 5, lane = tid & 31;
    int gid = lane >> 2, tig = lane & 3;
    int base = blockIdx.x * 128;

    // ---- Phase 1: per-thread edge features via quaternion composition ----
    {
        int e = base + tid;
        float f[23];
#pragma unroll
        for (int k = 0; k < 23; k++) f[k] = 0.0f;
        if (e < E) {
            int s = __ldg(ei + e);
            int t = __ldg(ei + E + e);

            float4 qt = g_qn[2 * t], xt = g_qn[2 * t + 1];
            float4 qs = g_qn[2 * s], xs = g_qn[2 * s + 1];

            float dvx = xs.x - xt.x, dvy = xs.y - xt.y, dvz = xs.z - xt.z;
            float d2   = dvx * dvx + dvy * dvy + dvz * dvz;
            float dist = sqrtf(d2 + 1e-6f);
            float rinv = 1.0f / fmaxf(sqrtf(d2), 1e-12f);
            float dhx = dvx * rinv, dhy = dvy * rinv, dhz = dvz * rinv;

            // q_rel = conj(q_t) * q_s
            float rw = qt.w * qs.w + qt.x * qs.x + qt.y * qs.y + qt.z * qs.z;
            float rx = qt.w * qs.x - qs.w * qt.x - (qt.y * qs.z - qt.z * qs.y);
            float ry = qt.w * qs.y - qs.w * qt.y - (qt.z * qs.x - qt.x * qs.z);
            float rz = qt.w * qs.z - qs.w * qt.z - (qt.x * qs.y - qt.y * qs.x);

            float sgnw = signf_(rw);
            float qn2 = rx * rx + ry * ry + rz * rz + rw * rw;
            float vm = (xt.w * xs.w) * sgnw / fmaxf(sqrtf(qn2), 1e-12f);
            f[0] = rx * vm; f[1] = ry * vm; f[2] = rz * vm; f[3] = rw * vm;

#pragma unroll
            for (int k = 0; k < 16; k++) {
                float mu = (float)k * (20.0f / 15.0f);
                float tt = (dist - mu) * 0.8f;
                f[4 + k] = __expf(-tt * tt);
            }

            // direct = rotate dhat by conj(q_t); mask by valid_t
            {
                float ax = qt.x, ay = qt.y, az = qt.z, aw = qt.w;
                float t1x = ay * dhz - az * dhy;
                float t1y = az * dhx - ax * dhz;
                float t1z = ax * dhy - ay * dhx;
                float ux = ay * t1z - az * t1y;
                float uy = az * t1x - ax * t1z;
                float uz = ax * t1y - ay * t1x;
                f[20] = (dhx - 2.0f * aw * t1x + 2.0f * ux) * xt.w;
                f[21] = (dhy - 2.0f * aw * t1y + 2.0f * uy) * xt.w;
                f[22] = (dhz - 2.0f * aw * t1z + 2.0f * uz) * xt.w;
            }
        }

        uint4* Av = reinterpret_cast<uint4*>(A_img + tid * 56);
#pragma unroll
        for (int g = 0; g < 7; g++) {
            uint32_t au[4];
#pragma unroll
            for (int h = 0; h < 4; h++) {
                int c0 = 8 * g + 2 * h, c1 = c0 + 1;
                float a0 = (c0 < 23) ? h16rt(f[c0])
                         : (c0 < 46) ? (f[c0 - 23] - h16rt(f[c0 - 23]))
                         : (c0 < 48) ? 1.0f : 0.0f;
                float a1 = (c1 < 23) ? h16rt(f[c1])
                         : (c1 < 46) ? (f[c1 - 23] - h16rt(f[c1 - 23]))
                         : (c1 < 48) ? 1.0f : 0.0f;
                au[h] = packh2(a0, a1);
            }
            Av[g] = make_uint4(au[0], au[1], au[2], au[3]);
        }
    }
    __syncthreads();

    // ---- B fragments + LN params ----
    uint32_t B0[3][4], B1[3][4];
#pragma unroll
    for (int s = 0; s < 3; s++)
#pragma unroll
        for (int jj = 0; jj < 4; jj++) {
            unsigned long long v = gBfrag[(s * 16 + (w * 4 + jj)) * 32 + lane];
            B0[s][jj] = (uint32_t)v;
            B1[s][jj] = (uint32_t)(v >> 32);
        }
    float2 gg2[4], bt2[4];
#pragma unroll
    for (int jj = 0; jj < 4; jj++) {
        int colb = 32 * w + 8 * tig + 2 * jj;
        gg2[jj] = *reinterpret_cast<const float2*>(ge + colb);
        bt2[jj] = *reinterpret_cast<const float2*>(bet + colb);
    }

    uint32_t aBase = smem_u32(A_img)
                   + ((lane & 7) + ((lane & 8) ? 8 : 0)) * 112
                   + ((lane & 16) ? 16 : 0);

    // ---- Phase 2: 8 row-groups of 16 edges, one sync each ----
#pragma unroll 1
    for (int rg = 0; rg < 8; rg++) {
        int buf = rg & 1;
        float C[4][4];
#pragma unroll
        for (int jj = 0; jj < 4; jj++)
#pragma unroll
            for (int q = 0; q < 4; q++) C[jj][q] = 0.0f;

        uint32_t aAddr = aBase + rg * (16 * 112);
#pragma unroll
        for (int s = 0; s < 3; s++) {
            uint32_t a0, a1, a2, a3;
            ldmatrix_x4(a0, a1, a2, a3, aAddr + s * 32);
#pragma unroll
            for (int jj = 0; jj < 4; jj++)
                mma16816h(C[jj], a0, a1, a2, a3, B0[s][jj], B1[s][jj]);
        }

        float s1A = 0.f, s2A = 0.f, s1B = 0.f, s2B = 0.f;
#pragma unroll
        for (int jj = 0; jj < 4; jj++) {
            s1A += C[jj][0] + C[jj][1];
            s2A += C[jj][0] * C[jj][0] + C[jj][1] * C[jj][1];
            s1B += C[jj][2] + C[jj][3];
            s2B += C[jj][2] * C[jj][2] + C[jj][3] * C[jj][3];
        }
#pragma unroll
        for (int o = 1; o <= 2; o <<= 1) {
            s1A += __shfl_xor_sync(0xffffffffu, s1A, o);
            s2A += __shfl_xor_sync(0xffffffffu, s2A, o);
            s1B += __shfl_xor_sync(0xffffffffu, s1B, o);
            s2B += __shfl_xor_sync(0xffffffffu, s2B, o);
        }
        if (tig == 0) {
            red[buf][gid][w]     = make_float2(s1A, s2A);
            red[buf][gid + 8][w] = make_float2(s1B, s2B);
        }
        __syncthreads();

        float u1 = 0.f, u2 = 0.f, v1 = 0.f, v2 = 0.f;
#pragma unroll
        for (int ww = 0; ww < 4; ww++) {
            float2 a = red[buf][gid][ww];
            float2 b = red[buf][gid + 8][ww];
            u1 += a.x; u2 += a.y;
            v1 += b.x; v2 += b.y;
        }
        float meanA = u1 * (1.0f / 128.0f);
        float invA  = rsqrtf(fmaxf(u2 * (1.0f / 128.0f) - meanA * meanA, 0.0f) + 1e-5f);
        float meanB = v1 * (1.0f / 128.0f);
        float invB  = rsqrtf(fmaxf(v2 * (1.0f / 128.0f) - meanB * meanB, 0.0f) + 1e-5f);

        int eA = base + rg * 16 + gid, eB = eA + 8;
        int colb = 32 * w + 8 * tig;
        if (eA < E) {
            float4 lo, hi;
            lo.x = (C[0][0] - meanA) * invA * gg2[0].x + bt2[0].x;
            lo.y = (C[0][1] - meanA) * invA * gg2[0].y + bt2[0].y;
            lo.z = (C[1][0] - meanA) * invA * gg2[1].x + bt2[1].x;
            lo.w = (C[1][1] - meanA) * invA * gg2[1].y + bt2[1].y;
            hi.x = (C[2][0] - meanA) * invA * gg2[2].x + bt2[2].x;
            hi.y = (C[2][1] - meanA) * invA * gg2[2].y + bt2[2].y;
            hi.z = (C[3][0] - meanA) * invA * gg2[3].x + bt2[3].x;
            hi.w = (C[3][1] - meanA) * invA * gg2[3].y + bt2[3].y;
            float* dst = hE + (size_t)eA * 128 + colb;
            __stcs(reinterpret_cast<float4*>(dst),     lo);
            __stcs(reinterpret_cast<float4*>(dst + 4), hi);
        }
        if (eB < E) {
            float4 lo, hi;
            lo.x = (C[0][2] - meanB) * invB * gg2[0].x + bt2[0].x;
            lo.y = (C[0][3] - meanB) * invB * gg2[0].y + bt2[0].y;
            lo.z = (C[1][2] - meanB) * invB * gg2[1].x + bt2[1].x;
            lo.w = (C[1][3] - meanB) * invB * gg2[1].y + bt2[1].y;
            hi.x = (C[2][2] - meanB) * invB * gg2[2].x + bt2[2].x;
            hi.y = (C[2][3] - meanB) * invB * gg2[2].y + bt2[2].y;
            hi.z = (C[3][2] - meanB) * invB * gg2[3].x + bt2[3].x;
            hi.w = (C[3][3] - meanB) * invB * gg2[3].y + bt2[3].y;
            float* dst = hE + (size_t)eB * 128 + colb;
            __stcs(reinterpret_cast<float4*>(dst),     lo);
            __stcs(reinterpret_cast<float4*>(dst + 4), hi);
        }
    }
}

// ---------------------------------------------------------------------------
extern "C" void kernel_launch(void* const* d_in, const int* in_sizes, int n_in,
                              void* d_out, int out_size)
{
    const float* X    = (const float*)d_in[0];
    const int*   bat  = (const int*)d_in[1];
    const int*   ei   = (const int*)d_in[2];
    const float* Wn   = (const float*)d_in[3];
    const float* bn   = (const float*)d_in[4];
    const float* gn   = (const float*)d_in[5];
    const float* btn  = (const float*)d_in[6];
    const float* We   = (const float*)d_in[7];
    const float* be   = (const float*)d_in[8];
    const float* ge   = (const float*)d_in[9];
    const float* bte  = (const float*)d_in[10];

    int N = in_sizes[0] / 3;
    int E = in_sizes[2] / 2;

    float* hV = (float*)d_out;
    float* hE = hV + (size_t)N * 128;

    k_node<<<(N + 255) / 256, 256>>>(X, bat, N, Wn, bn, gn, btn, We, be, hV);
    k_edge_fused<<<(E + 127) / 128, 128>>>(ei, E, ge, bte, hE);
}

// round 12
// speedup vs baseline: 2.8086x; 1.0822x over previous
#include <cuda_runtime.h>
#include <cuda_fp16.h>
#include <math.h>
#include <stdint.h>

#define NMAX 100000

// Scratch (module-static):
__device__ float4 g_qn[NMAX * 2];      // per-node: [0]=frame quaternion, [1]=(X, valid)
__device__ unsigned long long gBfrag[1536]; // B fragments [s(3)][j(16)][lane(32)]

struct F3 { float x, y, z; };
__device__ __forceinline__ F3 mk3(float a, float b, float c) { F3 r; r.x = a; r.y = b; r.z = c; return r; }
__device__ __forceinline__ F3 sub3(F3 a, F3 b) { return mk3(a.x - b.x, a.y - b.y, a.z - b.z); }
__device__ __forceinline__ float dot3(F3 a, F3 b) { return a.x * b.x + a.y * b.y + a.z * b.z; }
__device__ __forceinline__ F3 cross3(F3 a, F3 b) {
    return mk3(a.y * b.z - a.z * b.y, a.z * b.x - a.x * b.z, a.x * b.y - a.y * b.x);
}
__device__ __forceinline__ F3 nrm3(F3 a) {
    float n = sqrtf(dot3(a, a));
    float s = 1.0f / fmaxf(n, 1e-12f);
    return mk3(a.x * s, a.y * s, a.z * s);
}
__device__ __forceinline__ float signf_(float x) { return (float)((x > 0.0f) - (x < 0.0f)); }

__device__ __forceinline__ uint32_t smem_u32(const void* p) {
    uint32_t a;
    asm("{ .reg .u64 t; cvta.to.shared.u64 t, %1; cvt.u32.u64 %0, t; }" : "=r"(a) : "l"(p));
    return a;
}
__device__ __forceinline__ void mma16816h(float* c, uint32_t a0, uint32_t a1, uint32_t a2, uint32_t a3,
                                          uint32_t b0, uint32_t b1) {
    asm volatile(
        "mma.sync.aligned.m16n8k16.row.col.f32.f16.f16.f32 "
        "{%0,%1,%2,%3}, {%4,%5,%6,%7}, {%8,%9}, {%0,%1,%2,%3};"
        : "+f"(c[0]), "+f"(c[1]), "+f"(c[2]), "+f"(c[3])
        : "r"(a0), "r"(a1), "r"(a2), "r"(a3), "r"(b0), "r"(b1));
}
__device__ __forceinline__ void ldmatrix_x4(uint32_t& a0, uint32_t& a1, uint32_t& a2, uint32_t& a3, uint32_t addr) {
    asm volatile("ldmatrix.sync.aligned.m8n8.x4.shared.b16 {%0,%1,%2,%3}, [%4];"
                 : "=r"(a0), "=r"(a1), "=r"(a2), "=r"(a3) : "r"(addr));
}
__device__ __forceinline__ float h16rt(float x) {   // round-trip through fp16
    return __half2float(__float2half(x));
}
__device__ __forceinline__ uint32_t packh2(float a, float b) {
    __half2 p = __floats2half2_rn(a, b);
    return *reinterpret_cast<uint32_t*>(&p);
}

// ---------------------------------------------------------------------------
// Fused node kernel: per-thread geometry -> smem; warp-per-node matmul + LN.
// Block 0 additionally builds the fp16 B fragments for the edge GEMM.
// Block = 256 threads = 8 warps; covers 256 nodes.
// ---------------------------------------------------------------------------
__global__ void __launch_bounds__(256)
k_node(const float* __restrict__ X, const int* __restrict__ batch, int N,
       const float* __restrict__ Wn, const float* __restrict__ bn,
       const float* __restrict__ gn, const float* __restrict__ bet,
       const float* __restrict__ We, const float* __restrict__ be,
       float* __restrict__ hV)
{
    __shared__ float4 s_nf[256];

    int tid = threadIdx.x, w = tid >> 5, lane = tid & 31;
    int base = blockIdx.x * 256;
    int i = base + tid;

    // ---- block 0: build B fragments (K'=48) for the edge GEMM ----
    if (blockIdx.x == 0) {
#pragma unroll
        for (int u = 0; u < 6; u++) {
            int idx = tid + 256 * u;   // 6*256 = 1536
            int fl = idx & 31, j = (idx >> 5) & 15, s = idx >> 9;
            int fgid = fl >> 2, ftig = fl & 3;
            int fw = j >> 2, fjj = j & 3;
            int n = 32 * fw + 8 * (fgid >> 1) + 2 * fjj + (fgid & 1);
            auto wv = [&](int r) -> float {
                if (r < 23)  return h16rt(We[r * 128 + n]);
                if (r < 46)  return h16rt(We[(r - 23) * 128 + n]);
                if (r == 46) return h16rt(be[n]);
                if (r == 47) { float x = be[n]; return x - h16rt(x); }
                return 0.0f;
            };
            int k0 = 16 * s + 2 * ftig;
            uint32_t b0 = packh2(wv(k0),     wv(k0 + 1));
            uint32_t b1 = packh2(wv(k0 + 8), wv(k0 + 9));
            gBfrag[idx] = ((unsigned long long)b1 << 32) | b0;
        }
    }

    if (i < N) {
        auto ldx = [&](int j) -> F3 {
            j = j < 0 ? 0 : (j > N - 1 ? N - 1 : j);
            return mk3(X[3 * j], X[3 * j + 1], X[3 * j + 2]);
        };
        F3 xm1 = ldx(i - 1), x0 = ldx(i), xp1 = ldx(i + 1), xp2 = ldx(i + 2);

        int bi   = (i > 0)     && (batch[i] != batch[i - 1]);
        int bip1 = (i + 1 < N) && (batch[i + 1] != batch[i]);
        int bip2 = (i + 2 < N) && (batch[i + 2] != batch[i + 1]);
        bool bad_a = bi || bip1 || (i == 0) || (i == N - 1);
        bool bad_d = bi || bip1 || bip2 || (i == 0) || (i >= N - 2);

        F3 Um = nrm3(sub3(x0,  xm1));
        F3 Uc = nrm3(sub3(xp1, x0));
        F3 Up = nrm3(sub3(xp2, xp1));

        F3 c1 = nrm3(cross3(Um, Uc));
        F3 c2 = nrm3(cross3(Uc, Up));
        float cosd = fminf(fmaxf(dot3(c1, c2), -1.0f + 1e-6f), 1.0f - 1e-6f);
        float sg = signf_(dot3(c2, Um));
        float sdih = sg * sqrtf(fmaxf(1.0f - cosd * cosd, 0.0f));
        float cdih = (sg == 0.0f) ? 1.0f : cosd;

        F3 d0 = nrm3(sub3(xm1, x0));
        F3 d1 = nrm3(sub3(xp1, x0));
        float cosa = dot3(d0, d1);
        float sina = sqrtf(1.0f - cosa * cosa + 1e-6f);

        float4 nf;
        nf.x = bad_d ? 0.0f : sdih;
        nf.y = bad_d ? 0.0f : cdih;
        nf.z = bad_a ? 0.0f : sina;
        nf.w = bad_a ? 0.0f : cosa;
        s_nf[tid] = nf;

        // Local frame Q = [bv nv cv]; convert to quaternion (Shepperd).
        F3 bv = nrm3(sub3(Um, Uc));
        F3 nv = nrm3(cross3(Um, Uc));
        F3 cv = cross3(bv, nv);

        float qx = 0.0f, qy = 0.0f, qz = 0.0f, qw = 1.0f;
        if (!bad_a) {
            float m00 = bv.x, m10 = bv.y, m20 = bv.z;
            float m01 = nv.x, m11 = nv.y, m21 = nv.z;
            float m02 = cv.x, m12 = cv.y, m22 = cv.z;
            float tr = m00 + m11 + m22;
            if (tr > 0.0f) {
                float S = fmaxf(sqrtf(fmaxf(tr + 1.0f, 0.0f)) * 2.0f, 1e-20f);
                qw = 0.25f * S;
                qx = (m21 - m12) / S;
                qy = (m02 - m20) / S;
                qz = (m10 - m01) / S;
            } else if (m00 >= m11 && m00 >= m22) {
                float S = fmaxf(sqrtf(fmaxf(1.0f + m00 - m11 - m22, 0.0f)) * 2.0f, 1e-20f);
                qw = (m21 - m12) / S;
                qx = 0.25f * S;
                qy = (m01 + m10) / S;
                qz = (m02 + m20) / S;
            } else if (m11 >= m22) {
                float S = fmaxf(sqrtf(fmaxf(1.0f + m11 - m00 - m22, 0.0f)) * 2.0f, 1e-20f);
                qw = (m02 - m20) / S;
                qx = (m01 + m10) / S;
                qy = 0.25f * S;
                qz = (m12 + m21) / S;
            } else {
                float S = fmaxf(sqrtf(fmaxf(1.0f + m22 - m00 - m11, 0.0f)) * 2.0f, 1e-20f);
                qw = (m10 - m01) / S;
                qx = (m02 + m20) / S;
                qy = (m12 + m21) / S;
                qz = 0.25f * S;
            }
            float nq = rsqrtf(fmaxf(qx * qx + qy * qy + qz * qz + qw * qw, 1e-24f));
            qx *= nq; qy *= nq; qz *= nq; qw *= nq;
        }
        g_qn[i * 2 + 0] = make_float4(qx, qy, qz, qw);
        g_qn[i * 2 + 1] = make_float4(x0.x, x0.y, x0.z, bad_a ? 0.0f : 1.0f);
    } else {
        s_nf[tid] = make_float4(0.f, 0.f, 0.f, 0.f);
    }
    __syncthreads();

    // warp-per-node output: warp w handles local nodes 32w .. 32w+31
    int c = 4 * lane;
    float4 w0 = *reinterpret_cast<const float4*>(Wn + 0 * 128 + c);
    float4 w1 = *reinterpret_cast<const float4*>(Wn + 1 * 128 + c);
    float4 w2 = *reinterpret_cast<const float4*>(Wn + 2 * 128 + c);
    float4 w3 = *reinterpret_cast<const float4*>(Wn + 3 * 128 + c);
    float4 bb = *reinterpret_cast<const float4*>(bn + c);
    float4 gg = *reinterpret_cast<const float4*>(gn + c);
    float4 bt = *reinterpret_cast<const float4*>(bet + c);

#pragma unroll 1
    for (int it = 0; it < 32; it++) {
        int gw = base + 32 * w + it;
        if (gw >= N) break;
        float4 f = s_nf[32 * w + it];
        float4 a;
        a.x = bb.x + f.x * w0.x + f.y * w1.x + f.z * w2.x + f.w * w3.x;
        a.y = bb.y + f.x * w0.y + f.y * w1.y + f.z * w2.y + f.w * w3.y;
        a.z = bb.z + f.x * w0.z + f.y * w1.z + f.z * w2.z + f.w * w3.z;
        a.w = bb.w + f.x * w0.w + f.y * w1.w + f.z * w2.w + f.w * w3.w;

        float s1 = a.x + a.y + a.z + a.w;
        float s2 = a.x * a.x + a.y * a.y + a.z * a.z + a.w * a.w;
#pragma unroll
        for (int o = 16; o > 0; o >>= 1) {
            s1 += __shfl_xor_sync(0xffffffffu, s1, o);
            s2 += __shfl_xor_sync(0xffffffffu, s2, o);
        }
        float mean = s1 * (1.0f / 128.0f);
        float var  = fmaxf(s2 * (1.0f / 128.0f) - mean * mean, 0.0f);
        float inv  = rsqrtf(var + 1e-5f);
        float4 o4;
        o4.x = (a.x - mean) * inv * gg.x + bt.x;
        o4.y = (a.y - mean) * inv * gg.y + bt.y;
        o4.z = (a.z - mean) * inv * gg.z + bt.z;
        o4.w = (a.w - mean) * inv * gg.w + bt.w;
        __stcs(reinterpret_cast<float4*>(hV + (size_t)gw * 128 + c), o4);
    }
}

// ---------------------------------------------------------------------------
// FUSED edge features (quaternion path) + fp16 tensor GEMM + LN.
// Block = 128 threads = 4 warps; tile = 128 edges; K' = 48 (3 k-steps).
// A row: cols 0..22 = f16(f), 23..45 = f - f16(f), 46..47 = 1, 48..55 = 0.
// ---------------------------------------------------------------------------
__global__ void __launch_bounds__(128, 6)
k_edge_fused(const int* __restrict__ ei, int E,
             const float* __restrict__ ge, const float* __restrict__ bet,
             float* __restrict__ hE)
{
    __shared__ __half A_img[128 * 56];   // stride 56 f16 = 112 B (conflict-free)
    __shared__ float2 red[2][16][5];

    int tid = threadIdx.x, w = tid >> 5, lane = tid & 31;
    int gid = lane >> 2, tig = lane & 3;
    int base = blockIdx.x * 128;

    // ---- Phase 1: per-thread edge features via quaternion composition ----
    {
        int e = base + tid;
        float f[23];
#pragma unroll
        for (int k = 0; k < 23; k++) f[k] = 0.0f;
        if (e < E) {
            int s = __ldg(ei + e);
            int t = __ldg(ei + E + e);

            float4 qt = g_qn[2 * t], xt = g_qn[2 * t + 1];
            float4 qs = g_qn[2 * s], xs = g_qn[2 * s + 1];

            float dvx = xs.x - xt.x, dvy = xs.y - xt.y, dvz = xs.z - xt.z;
            float d2   = dvx * dvx + dvy * dvy + dvz * dvz;
            float dist = sqrtf(d2 + 1e-6f);
            float rinv = 1.0f / fmaxf(sqrtf(d2), 1e-12f);
            float dhx = dvx * rinv, dhy = dvy * rinv, dhz = dvz * rinv;

            // q_rel = conj(q_t) * q_s
            float rw = qt.w * qs.w + qt.x * qs.x + qt.y * qs.y + qt.z * qs.z;
            float rx = qt.w * qs.x - qs.w * qt.x - (qt.y * qs.z - qt.z * qs.y);
            float ry = qt.w * qs.y - qs.w * qt.y - (qt.z * qs.x - qt.x * qs.z);
            float rz = qt.w * qs.z - qs.w * qt.z - (qt.x * qs.y - qt.y * qs.x);

            float sgnw = signf_(rw);
            float qn2 = rx * rx + ry * ry + rz * rz + rw * rw;
            float vm = (xt.w * xs.w) * sgnw / fmaxf(sqrtf(qn2), 1e-12f);
            f[0] = rx * vm; f[1] = ry * vm; f[2] = rz * vm; f[3] = rw * vm;

#pragma unroll
            for (int k = 0; k < 16; k++) {
                float mu = (float)k * (20.0f / 15.0f);
                float tt = (dist - mu) * 0.8f;
                f[4 + k] = __expf(-tt * tt);
            }

            // direct = rotate dhat by conj(q_t); mask by valid_t
            {
                float ax = qt.x, ay = qt.y, az = qt.z, aw = qt.w;
                float t1x = ay * dhz - az * dhy;
                float t1y = az * dhx - ax * dhz;
                float t1z = ax * dhy - ay * dhx;
                float ux = ay * t1z - az * t1y;
                float uy = az * t1x - ax * t1z;
                float uz = ax * t1y - ay * t1x;
                f[20] = (dhx - 2.0f * aw * t1x + 2.0f * ux) * xt.w;
                f[21] = (dhy - 2.0f * aw * t1y + 2.0f * uy) * xt.w;
                f[22] = (dhz - 2.0f * aw * t1z + 2.0f * uz) * xt.w;
            }
        }

        uint4* Av = reinterpret_cast<uint4*>(A_img + tid * 56);
#pragma unroll
        for (int g = 0; g < 7; g++) {
            uint32_t au[4];
#pragma unroll
            for (int h = 0; h < 4; h++) {
                int c0 = 8 * g + 2 * h, c1 = c0 + 1;
                float a0 = (c0 < 23) ? h16rt(f[c0])
                         : (c0 < 46) ? (f[c0 - 23] - h16rt(f[c0 - 23]))
                         : (c0 < 48) ? 1.0f : 0.0f;
                float a1 = (c1 < 23) ? h16rt(f[c1])
                         : (c1 < 46) ? (f[c1 - 23] - h16rt(f[c1 - 23]))
                         : (c1 < 48) ? 1.0f : 0.0f;
                au[h] = packh2(a0, a1);
            }
            Av[g] = make_uint4(au[0], au[1], au[2], au[3]);
        }
    }
    __syncthreads();

    // ---- B fragments + LN params ----
    uint32_t B0[3][4], B1[3][4];
#pragma unroll
    for (int s = 0; s < 3; s++)
#pragma unroll
        for (int jj = 0; jj < 4; jj++) {
            unsigned long long v = gBfrag[(s * 16 + (w * 4 + jj)) * 32 + lane];
            B0[s][jj] = (uint32_t)v;
            B1[s][jj] = (uint32_t)(v >> 32);
        }
    float2 gg2[4], bt2[4];
#pragma unroll
    for (int jj = 0; jj < 4; jj++) {
        int colb = 32 * w + 8 * tig + 2 * jj;
        gg2[jj] = *reinterpret_cast<const float2*>(ge + colb);
        bt2[jj] = *reinterpret_cast<const float2*>(bet + colb);
    }

    uint32_t aBase = smem_u32(A_img)
                   + ((lane & 7) + ((lane & 8) ? 8 : 0)) * 112
                   + ((lane & 16) ? 16 : 0);

    // ---- Phase 2: 8 row-groups of 16 edges, one sync each ----
#pragma unroll 1
    for (int rg = 0; rg < 8; rg++) {
        int buf = rg & 1;
        float C[4][4];
#pragma unroll
        for (int jj = 0; jj < 4; jj++)
#pragma unroll
            for (int q = 0; q < 4; q++) C[jj][q] = 0.0f;

        uint32_t aAddr = aBase + rg * (16 * 112);
#pragma unroll
        for (int s = 0; s < 3; s++) {
            uint32_t a0, a1, a2, a3;
            ldmatrix_x4(a0, a1, a2, a3, aAddr + s * 32);
#pragma unroll
            for (int jj = 0; jj < 4; jj++)
                mma16816h(C[jj], a0, a1, a2, a3, B0[s][jj], B1[s][jj]);
        }

        float s1A = 0.f, s2A = 0.f, s1B = 0.f, s2B = 0.f;
#pragma unroll
        for (int jj = 0; jj < 4; jj++) {
            s1A += C[jj][0] + C[jj][1];
            s2A += C[jj][0] * C[jj][0] + C[jj][1] * C[jj][1];
            s1B += C[jj][2] + C[jj][3];
            s2B += C[jj][2] * C[jj][2] + C[jj][3] * C[jj][3];
        }
#pragma unroll
        for (int o = 1; o <= 2; o <<= 1) {
            s1A += __shfl_xor_sync(0xffffffffu, s1A, o);
            s2A += __shfl_xor_sync(0xffffffffu, s2A, o);
            s1B += __shfl_xor_sync(0xffffffffu, s1B, o);
            s2B += __shfl_xor_sync(0xffffffffu, s2B, o);
        }
        if (tig == 0) {
            red[buf][gid][w]     = make_float2(s1A, s2A);
            red[buf][gid + 8][w] = make_float2(s1B, s2B);
        }
        __syncthreads();

        float u1 = 0.f, u2 = 0.f, v1 = 0.f, v2 = 0.f;
#pragma unroll
        for (int ww = 0; ww < 4; ww++) {
            float2 a = red[buf][gid][ww];
            float2 b = red[buf][gid + 8][ww];
            u1 += a.x; u2 += a.y;
            v1 += b.x; v2 += b.y;
        }
        float meanA = u1 * (1.0f / 128.0f);
        float invA  = rsqrtf(fmaxf(u2 * (1.0f / 128.0f) - meanA * meanA, 0.0f) + 1e-5f);
        float meanB = v1 * (1.0f / 128.0f);
        float invB  = rsqrtf(fmaxf(v2 * (1.0f / 128.0f) - meanB * meanB, 0.0f) + 1e-5f);

        int eA = base + rg * 16 + gid, eB = eA + 8;
        int colb = 32 * w + 8 * tig;
        if (eA < E) {
            float4 lo, hi;
            lo.x = (C[0][0] - meanA) * invA * gg2[0].x + bt2[0].x;
            lo.y = (C[0][1] - meanA) * invA * gg2[0].y + bt2[0].y;
            lo.z = (C[1][0] - meanA) * invA * gg2[1].x + bt2[1].x;
            lo.w = (C[1][1] - meanA) * invA * gg2[1].y + bt2[1].y;
            hi.x = (C[2][0] - meanA) * invA * gg2[2].x + bt2[2].x;
            hi.y = (C[2][1] - meanA) * invA * gg2[2].y + bt2[2].y;
            hi.z = (C[3][0] - meanA) * invA * gg2[3].x + bt2[3].x;
            hi.w = (C[3][1] - meanA) * invA * gg2[3].y + bt2[3].y;
            float* dst = hE + (size_t)eA * 128 + colb;
            __stcs(reinterpret_cast<float4*>(dst),     lo);
            __stcs(reinterpret_cast<float4*>(dst + 4), hi);
        }
        if (eB < E) {
            float4 lo, hi;
            lo.x = (C[0][2] - meanB) * invB * gg2[0].x + bt2[0].x;
            lo.y = (C[0][3] - meanB) * invB * gg2[0].y + bt2[0].y;
            lo.z = (C[1][2] - meanB) * invB * gg2[1].x + bt2[1].x;
            lo.w = (C[1][3] - meanB) * invB * gg2[1].y + bt2[1].y;
            hi.x = (C[2][2] - meanB) * invB * gg2[2].x + bt2[2].x;
            hi.y = (C[2][3] - meanB) * invB * gg2[2].y + bt2[2].y;
            hi.z = (C[3][2] - meanB) * invB * gg2[3].x + bt2[3].x;
            hi.w = (C[3][3] - meanB) * invB * gg2[3].y + bt2[3].y;
            float* dst = hE + (size_t)eB * 128 + colb;
            __stcs(reinterpret_cast<float4*>(dst),     lo);
            __stcs(reinterpret_cast<float4*>(dst + 4), hi);
        }
    }
}

// ---------------------------------------------------------------------------
extern "C" void kernel_launch(void* const* d_in, const int* in_sizes, int n_in,
                              void* d_out, int out_size)
{
    const float* X    = (const float*)d_in[0];
    const int*   bat  = (const int*)d_in[1];
    const int*   ei   = (const int*)d_in[2];
    const float* Wn   = (const float*)d_in[3];
    const float* bn   = (const float*)d_in[4];
    const float* gn   = (const float*)d_in[5];
    const float* btn  = (const float*)d_in[6];
    const float* We   = (const float*)d_in[7];
    const float* be   = (const float*)d_in[8];
    const float* ge   = (const float*)d_in[9];
    const float* bte  = (const float*)d_in[10];

    int N = in_sizes[0] / 3;
    int E = in_sizes[2] / 2;

    float* hV = (float*)d_out;
    float* hE = hV + (size_t)N * 128;

    k_node<<<(N + 255) / 256, 256>>>(X, bat, N, Wn, bn, gn, btn, We, be, hV);
    k_edge_fused<<<(E + 127) / 128, 128>>>(ei, E, ge, bte, hE);
}